// round 10
// baseline (speedup 1.0000x reference)
#include <cuda_runtime.h>
#include <math.h>
#include <stdint.h>

#define NROWS 32768
#define DIN   960
#define DH    1920

// ---------------- static device buffers (no allocations) ----------------
__device__ float g_xp [(size_t)NROWS * DIN];   // x planar fp32
__device__ float g_h1 [(size_t)NROWS * DH];
__device__ float g_h2 [(size_t)NROWS * DH];
__device__ float g_outp[(size_t)NROWS * DIN];
__device__ float g_sum0[256];
__device__ float g_ssq[448];
__device__ float g_wt1[172032];   // transposed [Nout,K] fp32, alpha folded
__device__ float g_wt2[344064];
__device__ float g_wt3[172032];
__device__ float g_wtb[86016];

// ---------------- helpers ----------------
__device__ __forceinline__ uint32_t s2u(const void* p) {
    uint32_t a;
    asm("{ .reg .u64 t; cvta.to.shared.u64 t, %1; cvt.u32.u64 %0, t; }"
        : "=r"(a) : "l"(p));
    return a;
}

__device__ __forceinline__ void cp16(uint32_t dst, const void* src) {
    asm volatile("cp.async.cg.shared.global [%0], [%1], 16;"
                 :: "r"(dst), "l"(src));
}

__device__ __forceinline__ uint32_t f2tf(float x) {
    uint32_t r;
    asm("cvt.rna.tf32.f32 %0, %1;" : "=r"(r) : "f"(x));
    return r;
}

__device__ __forceinline__ void mma_tf32(float* d, const uint32_t* a,
                                         uint32_t b0, uint32_t b1) {
    asm volatile(
        "mma.sync.aligned.m16n8k8.row.col.f32.tf32.tf32.f32 "
        "{%0,%1,%2,%3}, {%4,%5,%6,%7}, {%8,%9}, {%0,%1,%2,%3};"
        : "+f"(d[0]), "+f"(d[1]), "+f"(d[2]), "+f"(d[3])
        : "r"(a[0]), "r"(a[1]), "r"(a[2]), "r"(a[3]), "r"(b0), "r"(b1));
}

// ---------------- 3xTF32 GEMM, two concatenated operand sets ----------------
// C[M, Nout] = A1[M,K1] @ B1[Nout,K1]^T + A2[M,K2] @ B2[Nout,K2]^T
// (fp32 in/out, 3xTF32 hi/lo split products: hh + hl + lh)
// 4-stage cp.async pipeline, ONE __syncthreads per chunk, cp.async issue
// overlapped with the MMA block of the same chunk.
// BM=128, BN=128 or 64, BK=16, 256 threads.
// act=1: apply f*sigmoid(|f|)/|f| (l=0 NormActivation) elementwise in epilogue.
template <int BN>
__global__ __launch_bounds__(256, 2) void gemm_tf32(
    const float* __restrict__ A1, int lda1, size_t sAz1,
    const float* __restrict__ B1, int ldb1, int nc1,
    const float* __restrict__ A2, int lda2, size_t sAz2,
    const float* __restrict__ B2, int ldb2, int nc2,
    float* __restrict__ C, int ldc, size_t sCz, int act)
{
    constexpr int WN = (BN == 128) ? 4 : 2;   // warps along N
    constexpr int MT = (BN == 128) ? 4 : 2;   // m16-tiles per warp
    constexpr int ST = 4;
    extern __shared__ float dsm[];
    float* sAb = dsm;                   // [ST][128*20]
    float* sBb = dsm + ST * 128 * 20;   // [ST][BN*20]

    A1 += (size_t)blockIdx.z * sAz1;
    A2 += (size_t)blockIdx.z * sAz2;
    C  += (size_t)blockIdx.z * sCz;

    const int tid = threadIdx.x, wid = tid >> 5, lane = tid & 31;
    const int g = lane >> 2, t = lane & 3;
    const int wm = wid / WN, wn = wid % WN;
    const int row0 = blockIdx.y << 7;
    const int n0   = blockIdx.x * BN;
    const int tot  = nc1 + nc2;

    float acc[MT][4][4] = {};

    auto issue = [&](int cc) {
        if (cc < tot) {
            const int s = cc & 3;
            const float* Asrc; const float* Bsrc; int la, lb;
            if (cc < nc1) {
                Asrc = A1 + (size_t)row0 * lda1 + cc * 16;
                Bsrc = B1 + (size_t)n0 * ldb1 + cc * 16;
                la = lda1; lb = ldb1;
            } else {
                int c2 = cc - nc1;
                Asrc = A2 + (size_t)row0 * lda2 + c2 * 16;
                Bsrc = B2 + (size_t)n0 * ldb2 + c2 * 16;
                la = lda2; lb = ldb2;
            }
            uint32_t da = s2u(sAb + s * (128 * 20));
            #pragma unroll
            for (int i = tid; i < 512; i += 256) {
                int r = i >> 2, u = i & 3;
                cp16(da + r * 80 + u * 16, Asrc + (size_t)r * la + u * 4);
            }
            uint32_t db = s2u(sBb + s * (BN * 20));
            #pragma unroll
            for (int i = tid; i < BN * 4; i += 256) {
                int r = i >> 2, u = i & 3;
                cp16(db + r * 80 + u * 16, Bsrc + (size_t)r * lb + u * 4);
            }
        }
        asm volatile("cp.async.commit_group;");
    };

    issue(0); issue(1); issue(2);

    for (int cc = 0; cc < tot; cc++) {
        asm volatile("cp.async.wait_group 2;");
        __syncthreads();
        // refill stage (cc-1)%4 = (cc+3)%4 — consumed last chunk, safe after sync.
        issue(cc + 3);

        const int s = cc & 3;
        const float* a = sAb + s * (128 * 20);
        const float* b = sBb + s * (BN * 20);

        #pragma unroll
        for (int ks = 0; ks < 2; ks++) {
            const int kb = ks * 8;
            uint32_t bhi[4][2], blo[4][2];
            #pragma unroll
            for (int nt = 0; nt < 4; nt++) {
                int nr = wn * 32 + nt * 8 + g;
                float f0 = b[nr * 20 + kb + t];
                float f1 = b[nr * 20 + kb + 4 + t];
                bhi[nt][0] = f2tf(f0);
                blo[nt][0] = f2tf(f0 - __uint_as_float(bhi[nt][0]));
                bhi[nt][1] = f2tf(f1);
                blo[nt][1] = f2tf(f1 - __uint_as_float(bhi[nt][1]));
            }
            #pragma unroll
            for (int mp = 0; mp < MT / 2; mp++) {
                uint32_t ahi[2][4], alo[2][4];
                #pragma unroll
                for (int q = 0; q < 2; q++) {
                    int r0 = wm * (MT * 16) + (mp * 2 + q) * 16 + g;
                    float a0 = a[r0 * 20 + kb + t];
                    float a1 = a[(r0 + 8) * 20 + kb + t];
                    float a2 = a[r0 * 20 + kb + 4 + t];
                    float a3 = a[(r0 + 8) * 20 + kb + 4 + t];
                    ahi[q][0] = f2tf(a0); alo[q][0] = f2tf(a0 - __uint_as_float(ahi[q][0]));
                    ahi[q][1] = f2tf(a1); alo[q][1] = f2tf(a1 - __uint_as_float(ahi[q][1]));
                    ahi[q][2] = f2tf(a2); alo[q][2] = f2tf(a2 - __uint_as_float(ahi[q][2]));
                    ahi[q][3] = f2tf(a3); alo[q][3] = f2tf(a3 - __uint_as_float(ahi[q][3]));
                }
                // per-accumulator order remains hh -> hl -> lh (numerics preserved).
                #pragma unroll
                for (int q = 0; q < 2; q++)
                    #pragma unroll
                    for (int nt = 0; nt < 4; nt++)
                        mma_tf32(acc[mp * 2 + q][nt], ahi[q], bhi[nt][0], bhi[nt][1]);
                #pragma unroll
                for (int q = 0; q < 2; q++)
                    #pragma unroll
                    for (int nt = 0; nt < 4; nt++)
                        mma_tf32(acc[mp * 2 + q][nt], ahi[q], blo[nt][0], blo[nt][1]);
                #pragma unroll
                for (int q = 0; q < 2; q++)
                    #pragma unroll
                    for (int nt = 0; nt < 4; nt++)
                        mma_tf32(acc[mp * 2 + q][nt], alo[q], bhi[nt][0], bhi[nt][1]);
            }
        }
    }

    // epilogue
    const int tig = lane & 3;
    #pragma unroll
    for (int mt = 0; mt < MT; mt++) {
        int r = row0 + wm * (MT * 16) + mt * 16 + g;
        #pragma unroll
        for (int nt = 0; nt < 4; nt++) {
            int cI = n0 + wn * 32 + nt * 8 + tig * 2;
            float v[4] = {acc[mt][nt][0], acc[mt][nt][1],
                          acc[mt][nt][2], acc[mt][nt][3]};
            if (act) {
                #pragma unroll
                for (int q = 0; q < 4; q++) {
                    float nn = sqrtf(v[q] * v[q] + 1e-8f);
                    float sg = 1.0f / (1.0f + expf(-nn));
                    v[q] = v[q] * sg / nn;
                }
            }
            float* p0 = C + (size_t)r * ldc + cI;
            float* p1 = p0 + (size_t)8 * ldc;
            *(float2*)p0 = make_float2(v[0], v[1]);
            *(float2*)p1 = make_float2(v[2], v[3]);
        }
    }
}

// ---------------- fused weight prep: all 12 segments in one launch ----------
__global__ void conv_w_all(const float* __restrict__ w1, const float* __restrict__ w2,
                           const float* __restrict__ w3, const float* __restrict__ wb,
                           float* __restrict__ t1, float* __restrict__ t2,
                           float* __restrict__ t3, float* __restrict__ tb) {
    int idx = blockIdx.x * 256 + threadIdx.x;
    if (idx >= 774144) return;
    const int ends[12] = {131072, 163840, 172032, 434176, 499712, 516096,
                          647168, 679936, 688128, 753664, 770048, 774144};
    const int Ks[12]   = {256, 128, 64, 512, 256, 128, 512, 256, 128, 256, 128, 64};
    const int Ns[12]   = {512, 256, 128, 512, 256, 128, 256, 128, 64, 256, 128, 64};
    int sidx = 0;
    while (idx >= ends[sidx]) sidx++;
    int start = sidx ? ends[sidx - 1] : 0;
    const float* src; float* dst; int tbase;
    if (sidx < 3)      { src = w1; dst = t1; tbase = 0; }
    else if (sidx < 6) { src = w2; dst = t2; tbase = 172032; }
    else if (sidx < 9) { src = w3; dst = t3; tbase = 516096; }
    else               { src = wb; dst = tb; tbase = 688128; }
    int segoff = start - tbase;
    int local  = idx - start;
    int K = Ks[sidx], Nout = Ns[sidx];
    int u = local / Nout, v = local - u * Nout;
    float alpha = 1.0f / sqrtf((float)K);
    dst[segoff + (size_t)v * K + u] = src[segoff + local] * alpha;
}

// ---------------- x interleaved -> planar fp32 ----------------
__global__ void to_planar_kernel(const float* __restrict__ x) {
    int idx = blockIdx.x * 256 + threadIdx.x;
    if (idx >= NROWS * DIN) return;
    int n = idx / DIN, j = idx - n * DIN;
    int src;
    if (j < 256) {
        src = j;
    } else if (j < 640) {
        int p = j - 256;
        src = 256 + (p & 127) * 3 + (p >> 7);
    } else {
        int p = j - 640;
        src = 640 + (p & 63) * 5 + (p >> 6);
    }
    g_xp[idx] = x[(size_t)n * DIN + src];
}

// ---------------- NormActivation l>0 (in place, planar fp32) ----------------
template <int L>
__global__ void normact_kernel(float* __restrict__ H, int o, int m) {
    int idx = blockIdx.x * 256 + threadIdx.x;
    if (idx >= NROWS * m) return;
    int n = idx / m, v = idx - n * m;
    float* p = H + (size_t)n * DH + o + v;
    float f[L];
    float s2 = 1e-8f;
    #pragma unroll
    for (int i = 0; i < L; i++) { f[i] = p[(size_t)i * m]; s2 += f[i] * f[i]; }
    float nn = sqrtf(s2);
    float sg = 1.0f / (1.0f + expf(-nn));
    float sc = sg / nn;
    #pragma unroll
    for (int i = 0; i < L; i++) p[(size_t)i * m] = f[i] * sc;
}

// ---------------- BatchNorm ----------------
__global__ void bn_zero_kernel() {
    int t = threadIdx.x;
    if (t < 256) g_sum0[t] = 0.0f;
    if (t < 448) g_ssq[t]  = 0.0f;
}

__global__ void bn_reduce_kernel() {
    const int tid = threadIdx.x;
    const int r0  = blockIdx.x * 128;     // 256 blocks * 128 rows
    float s[4] = {0, 0, 0, 0}, q[4] = {0, 0, 0, 0};
    for (int r = 0; r < 128; r++) {
        const float* row = g_outp + (size_t)(r0 + r) * DIN;
        #pragma unroll
        for (int k = 0; k < 4; k++) {
            int j = tid + (k << 8);
            if (j < DIN) {
                float v = row[j];
                s[k] += v;
                q[k] += v * v;
            }
        }
    }
    #pragma unroll
    for (int k = 0; k < 4; k++) {
        int j = tid + (k << 8);
        if (j >= DIN) continue;
        if (j < 256) {
            atomicAdd(&g_sum0[j], s[k]);
            atomicAdd(&g_ssq[j], q[k]);
        } else if (j < 640) {
            atomicAdd(&g_ssq[256 + ((j - 256) & 127)], q[k]);
        } else {
            atomicAdd(&g_ssq[384 + ((j - 640) & 63)], q[k]);
        }
    }
}

__global__ void bn_apply_kernel(const float* __restrict__ bnw,
                                const float* __restrict__ bnb,
                                float* __restrict__ out) {
    int idx = blockIdx.x * 256 + threadIdx.x;
    if (idx >= NROWS * DIN) return;
    int n = idx / DIN, jo = idx - n * DIN;
    const float invN = 1.0f / (float)NROWS;
    float g;
    if (jo < 256) {
        float f   = g_outp[(size_t)n * DIN + jo];
        float mu  = g_sum0[jo] * invN;
        float var = g_ssq[jo] * invN - mu * mu;
        g = (f - mu) * bnw[jo] * rsqrtf(var + 1e-5f) + bnb[jo];
    } else if (jo < 640) {
        int p = jo - 256, v = p / 3, i = p - v * 3;
        float f  = g_outp[(size_t)n * DIN + 256 + (i << 7) + v];
        float n2 = g_ssq[256 + v] * (invN * (1.0f / 3.0f));
        g = f * bnw[256 + v] * rsqrtf(n2 + 1e-5f);
    } else {
        int p = jo - 640, v = p / 5, i = p - v * 5;
        float f  = g_outp[(size_t)n * DIN + 640 + (i << 6) + v];
        float n2 = g_ssq[384 + v] * (invN * (1.0f / 5.0f));
        g = f * bnw[384 + v] * rsqrtf(n2 + 1e-5f);
    }
    out[idx] = g;
}

// ---------------- launch ----------------
#define SMEM128 (4 * (128 * 20 + 128 * 20) * 4)   // 81920
#define SMEM64  (4 * (128 * 20 + 64 * 20) * 4)    // 61440

extern "C" void kernel_launch(void* const* d_in, const int* in_sizes, int n_in,
                              void* d_out, int out_size) {
    const float* x   = (const float*)d_in[0];
    const float* w1  = (const float*)d_in[1];
    const float* w2  = (const float*)d_in[2];
    const float* w3  = (const float*)d_in[3];
    const float* wb  = (const float*)d_in[4];
    const float* bnw = (const float*)d_in[5];
    const float* bnb = (const float*)d_in[6];
    float* out = (float*)d_out;

    cudaFuncSetAttribute(gemm_tf32<128>, cudaFuncAttributeMaxDynamicSharedMemorySize, SMEM128);
    cudaFuncSetAttribute(gemm_tf32<64>,  cudaFuncAttributeMaxDynamicSharedMemorySize, SMEM64);

    float *xp, *h1, *h2, *op, *wt1, *wt2, *wt3, *wtb;
    cudaGetSymbolAddress((void**)&xp,  g_xp);
    cudaGetSymbolAddress((void**)&h1,  g_h1);
    cudaGetSymbolAddress((void**)&h2,  g_h2);
    cudaGetSymbolAddress((void**)&op,  g_outp);
    cudaGetSymbolAddress((void**)&wt1, g_wt1);
    cudaGetSymbolAddress((void**)&wt2, g_wt2);
    cudaGetSymbolAddress((void**)&wt3, g_wt3);
    cudaGetSymbolAddress((void**)&wtb, g_wtb);

    conv_w_all<<<3024, 256>>>(w1, w2, w3, wb, wt1, wt2, wt3, wtb);
    to_planar_kernel<<<(NROWS * DIN) / 256, 256>>>(x);

    auto gemm = [&](const float* A, int lda, size_t sAz, const float* B,
                    float* Cp, int ldc, size_t sCz,
                    int K, int Nout, int nz, int act) {
        if (Nout >= 128) {
            dim3 grid(Nout / 128, NROWS / 128, nz);
            gemm_tf32<128><<<grid, 256, SMEM128>>>(
                A, lda, sAz, B, K, K / 16,
                A, lda, sAz, B, K, 0,
                Cp, ldc, sCz, act);
        } else {
            dim3 grid(Nout / 64, NROWS / 128, nz);
            gemm_tf32<64><<<grid, 256, SMEM64>>>(
                A, lda, sAz, B, K, K / 16,
                A, lda, sAz, B, K, 0,
                Cp, ldc, sCz, act);
        }
    };
    auto gemm2 = [&](const float* A1p, int lda1, size_t sAz1, const float* B1, int K1,
                     const float* A2p, int lda2, size_t sAz2, const float* B2, int K2,
                     float* Cp, int ldc, size_t sCz, int Nout, int nz) {
        if (Nout >= 128) {
            dim3 grid(Nout / 128, NROWS / 128, nz);
            gemm_tf32<128><<<grid, 256, SMEM128>>>(
                A1p, lda1, sAz1, B1, K1, K1 / 16,
                A2p, lda2, sAz2, B2, K2, K2 / 16,
                Cp, ldc, sCz, 0);
        } else {
            dim3 grid(Nout / 64, NROWS / 128, nz);
            gemm_tf32<64><<<grid, 256, SMEM64>>>(
                A1p, lda1, sAz1, B1, K1, K1 / 16,
                A2p, lda2, sAz2, B2, K2, K2 / 16,
                Cp, ldc, sCz, 0);
        }
    };

    // layer 1: xp -> h1   (l0 gemm fuses scalar NormActivation)
    gemm(xp,        DIN, 0,   wt1,          h1,        DH, 0,   256, 512, 1, 1);
    gemm(xp + 256,  DIN, 128, wt1 + 131072, h1 + 512,  DH, 256, 128, 256, 3, 0);
    gemm(xp + 640,  DIN, 64,  wt1 + 163840, h1 + 1280, DH, 128,  64, 128, 5, 0);

    normact_kernel<3><<<(NROWS * 256) / 256, 256>>>(h1, 512, 256);
    normact_kernel<5><<<(NROWS * 128) / 256, 256>>>(h1, 1280, 128);

    // layer 2: h1 -> h2   (l0 gemm fuses scalar NormActivation)
    gemm(h1,        DH, 0,    wt2,          h2,        DH, 0,   512, 512, 1, 1);
    gemm(h1 + 512,  DH, 256,  wt2 + 262144, h2 + 512,  DH, 256, 256, 256, 3, 0);
    gemm(h1 + 1280, DH, 128,  wt2 + 327680, h2 + 1280, DH, 128, 128, 128, 5, 0);

    normact_kernel<3><<<(NROWS * 256) / 256, 256>>>(h2, 512, 256);
    normact_kernel<5><<<(NROWS * 128) / 256, 256>>>(h2, 1280, 128);

    // layer 3 + skip, fused concat-K: op = h2@W3 + xp@Wb
    gemm2(h2,        DH, 0,   wt3,          512, xp,       DIN, 0,   wtb,         256,
          op,       DIN, 0,   256, 1);
    gemm2(h2 + 512,  DH, 256, wt3 + 131072, 256, xp + 256, DIN, 128, wtb + 65536, 128,
          op + 256, DIN, 128, 128, 3);
    gemm2(h2 + 1280, DH, 128, wt3 + 163840, 128, xp + 640, DIN, 64,  wtb + 81920,  64,
          op + 640, DIN, 64,   64, 5);

    // batch norm -> interleaved fp32 output
    bn_zero_kernel<<<1, 512>>>();
    bn_reduce_kernel<<<256, 256>>>();
    bn_apply_kernel<<<(NROWS * DIN) / 256, 256>>>(bnw, bnb, out);
}

// round 11
// speedup vs baseline: 1.0034x; 1.0034x over previous
#include <cuda_runtime.h>
#include <math.h>
#include <stdint.h>

#define NROWS 32768
#define DIN   960
#define DH    1920

// ---------------- static device buffers (no allocations) ----------------
__device__ float g_xp [(size_t)NROWS * DIN];   // x planar fp32
__device__ float g_h1 [(size_t)NROWS * DH];
__device__ float g_h2 [(size_t)NROWS * DH];
__device__ float g_outp[(size_t)NROWS * DIN];
__device__ float g_sum0[256];
__device__ float g_ssq[448];
__device__ float g_wt1[172032];   // transposed [Nout,K] fp32, alpha folded
__device__ float g_wt2[344064];
__device__ float g_wt3[172032];
__device__ float g_wtb[86016];

// ---------------- helpers ----------------
__device__ __forceinline__ uint32_t s2u(const void* p) {
    uint32_t a;
    asm("{ .reg .u64 t; cvta.to.shared.u64 t, %1; cvt.u32.u64 %0, t; }"
        : "=r"(a) : "l"(p));
    return a;
}

__device__ __forceinline__ void cp16(uint32_t dst, const void* src) {
    asm volatile("cp.async.cg.shared.global [%0], [%1], 16;"
                 :: "r"(dst), "l"(src));
}

__device__ __forceinline__ uint32_t f2tf(float x) {
    uint32_t r;
    asm("cvt.rna.tf32.f32 %0, %1;" : "=r"(r) : "f"(x));
    return r;
}

__device__ __forceinline__ void mma_tf32(float* d, const uint32_t* a,
                                         uint32_t b0, uint32_t b1) {
    asm volatile(
        "mma.sync.aligned.m16n8k8.row.col.f32.tf32.tf32.f32 "
        "{%0,%1,%2,%3}, {%4,%5,%6,%7}, {%8,%9}, {%0,%1,%2,%3};"
        : "+f"(d[0]), "+f"(d[1]), "+f"(d[2]), "+f"(d[3])
        : "r"(a[0]), "r"(a[1]), "r"(a[2]), "r"(a[3]), "r"(b0), "r"(b1));
}

// ---------------- 3xTF32 GEMM, two concatenated operand sets ----------------
// C[M, Nout] = A1[M,K1] @ B1[Nout,K1]^T + A2[M,K2] @ B2[Nout,K2]^T
// (fp32 in/out, 3xTF32 hi/lo split products: hh + hl + lh)
// BM=128, BN=64 (warp tile 32x32, acc=32 regs), 256 threads, 3 CTAs/SM,
// 3-stage cp.async pipeline.
// act=1: apply f*sigmoid(|f|)/|f| (l=0 NormActivation) elementwise in epilogue.
__global__ __launch_bounds__(256, 3) void gemm_tf32(
    const float* __restrict__ A1, int lda1, size_t sAz1,
    const float* __restrict__ B1, int ldb1, int nc1,
    const float* __restrict__ A2, int lda2, size_t sAz2,
    const float* __restrict__ B2, int ldb2, int nc2,
    float* __restrict__ C, int ldc, size_t sCz, int act)
{
    constexpr int BN = 64;
    constexpr int MT = 2;              // m16-tiles per warp (32 rows)
    constexpr int ST = 3;
    extern __shared__ float dsm[];
    float* sAb = dsm;                   // [ST][128*20]
    float* sBb = dsm + ST * 128 * 20;   // [ST][64*20]

    A1 += (size_t)blockIdx.z * sAz1;
    A2 += (size_t)blockIdx.z * sAz2;
    C  += (size_t)blockIdx.z * sCz;

    const int tid = threadIdx.x, wid = tid >> 5, lane = tid & 31;
    const int g = lane >> 2, t = lane & 3;
    const int wm = wid >> 1, wn = wid & 1;   // 4 x 2 warp grid
    const int row0 = blockIdx.y << 7;
    const int n0   = blockIdx.x * BN;
    const int tot  = nc1 + nc2;

    float acc[MT][4][4] = {};

    auto issue = [&](int cc, int s) {
        if (cc < tot) {
            const float* Asrc; const float* Bsrc; int la, lb;
            if (cc < nc1) {
                Asrc = A1 + (size_t)row0 * lda1 + cc * 16;
                Bsrc = B1 + (size_t)n0 * ldb1 + cc * 16;
                la = lda1; lb = ldb1;
            } else {
                int c2 = cc - nc1;
                Asrc = A2 + (size_t)row0 * lda2 + c2 * 16;
                Bsrc = B2 + (size_t)n0 * ldb2 + c2 * 16;
                la = lda2; lb = ldb2;
            }
            uint32_t da = s2u(sAb + s * (128 * 20));
            #pragma unroll
            for (int i = tid; i < 512; i += 256) {
                int r = i >> 2, u = i & 3;
                cp16(da + r * 80 + u * 16, Asrc + (size_t)r * la + u * 4);
            }
            uint32_t db = s2u(sBb + s * (BN * 20));
            #pragma unroll
            for (int i = tid; i < BN * 4; i += 256) {
                int r = i >> 2, u = i & 3;
                cp16(db + r * 80 + u * 16, Bsrc + (size_t)r * lb + u * 4);
            }
        }
        asm volatile("cp.async.commit_group;");
    };

    issue(0, 0); issue(1, 1); issue(2, 2);

    for (int cc = 0; cc < tot; cc++) {
        asm volatile("cp.async.wait_group 2;");
        __syncthreads();

        const int s = cc % ST;
        const float* a = sAb + s * (128 * 20);
        const float* b = sBb + s * (BN * 20);

        #pragma unroll
        for (int ks = 0; ks < 2; ks++) {
            const int kb = ks * 8;
            uint32_t bhi[4][2], blo[4][2];
            #pragma unroll
            for (int nt = 0; nt < 4; nt++) {
                int nr = wn * 32 + nt * 8 + g;
                float f0 = b[nr * 20 + kb + t];
                float f1 = b[nr * 20 + kb + 4 + t];
                bhi[nt][0] = f2tf(f0);
                blo[nt][0] = f2tf(f0 - __uint_as_float(bhi[nt][0]));
                bhi[nt][1] = f2tf(f1);
                blo[nt][1] = f2tf(f1 - __uint_as_float(bhi[nt][1]));
            }
            uint32_t ahi[2][4], alo[2][4];
            #pragma unroll
            for (int q = 0; q < 2; q++) {
                int r0 = wm * 32 + q * 16 + g;
                float a0 = a[r0 * 20 + kb + t];
                float a1 = a[(r0 + 8) * 20 + kb + t];
                float a2 = a[r0 * 20 + kb + 4 + t];
                float a3 = a[(r0 + 8) * 20 + kb + 4 + t];
                ahi[q][0] = f2tf(a0); alo[q][0] = f2tf(a0 - __uint_as_float(ahi[q][0]));
                ahi[q][1] = f2tf(a1); alo[q][1] = f2tf(a1 - __uint_as_float(ahi[q][1]));
                ahi[q][2] = f2tf(a2); alo[q][2] = f2tf(a2 - __uint_as_float(ahi[q][2]));
                ahi[q][3] = f2tf(a3); alo[q][3] = f2tf(a3 - __uint_as_float(ahi[q][3]));
            }
            // per-accumulator order: hh -> hl -> lh (numerics preserved)
            #pragma unroll
            for (int q = 0; q < 2; q++)
                #pragma unroll
                for (int nt = 0; nt < 4; nt++)
                    mma_tf32(acc[q][nt], ahi[q], bhi[nt][0], bhi[nt][1]);
            #pragma unroll
            for (int q = 0; q < 2; q++)
                #pragma unroll
                for (int nt = 0; nt < 4; nt++)
                    mma_tf32(acc[q][nt], ahi[q], blo[nt][0], blo[nt][1]);
            #pragma unroll
            for (int q = 0; q < 2; q++)
                #pragma unroll
                for (int nt = 0; nt < 4; nt++)
                    mma_tf32(acc[q][nt], alo[q], bhi[nt][0], bhi[nt][1]);
        }
        __syncthreads();
        issue(cc + 3, s);
    }

    // epilogue
    const int tig = lane & 3;
    #pragma unroll
    for (int mt = 0; mt < MT; mt++) {
        int r = row0 + wm * 32 + mt * 16 + g;
        #pragma unroll
        for (int nt = 0; nt < 4; nt++) {
            int cI = n0 + wn * 32 + nt * 8 + tig * 2;
            float v[4] = {acc[mt][nt][0], acc[mt][nt][1],
                          acc[mt][nt][2], acc[mt][nt][3]};
            if (act) {
                #pragma unroll
                for (int q = 0; q < 4; q++) {
                    float nn = sqrtf(v[q] * v[q] + 1e-8f);
                    float sg = 1.0f / (1.0f + expf(-nn));
                    v[q] = v[q] * sg / nn;
                }
            }
            float* p0 = C + (size_t)r * ldc + cI;
            float* p1 = p0 + (size_t)8 * ldc;
            *(float2*)p0 = make_float2(v[0], v[1]);
            *(float2*)p1 = make_float2(v[2], v[3]);
        }
    }
}

// ---------------- fused weight prep: all 12 segments in one launch ----------
__global__ void conv_w_all(const float* __restrict__ w1, const float* __restrict__ w2,
                           const float* __restrict__ w3, const float* __restrict__ wb,
                           float* __restrict__ t1, float* __restrict__ t2,
                           float* __restrict__ t3, float* __restrict__ tb) {
    int idx = blockIdx.x * 256 + threadIdx.x;
    if (idx >= 774144) return;
    const int ends[12] = {131072, 163840, 172032, 434176, 499712, 516096,
                          647168, 679936, 688128, 753664, 770048, 774144};
    const int Ks[12]   = {256, 128, 64, 512, 256, 128, 512, 256, 128, 256, 128, 64};
    const int Ns[12]   = {512, 256, 128, 512, 256, 128, 256, 128, 64, 256, 128, 64};
    int sidx = 0;
    while (idx >= ends[sidx]) sidx++;
    int start = sidx ? ends[sidx - 1] : 0;
    const float* src; float* dst; int tbase;
    if (sidx < 3)      { src = w1; dst = t1; tbase = 0; }
    else if (sidx < 6) { src = w2; dst = t2; tbase = 172032; }
    else if (sidx < 9) { src = w3; dst = t3; tbase = 516096; }
    else               { src = wb; dst = tb; tbase = 688128; }
    int segoff = start - tbase;
    int local  = idx - start;
    int K = Ks[sidx], Nout = Ns[sidx];
    int u = local / Nout, v = local - u * Nout;
    float alpha = 1.0f / sqrtf((float)K);
    dst[segoff + (size_t)v * K + u] = src[segoff + local] * alpha;
}

// ---------------- x interleaved -> planar fp32 ----------------
__global__ void to_planar_kernel(const float* __restrict__ x) {
    int idx = blockIdx.x * 256 + threadIdx.x;
    if (idx >= NROWS * DIN) return;
    int n = idx / DIN, j = idx - n * DIN;
    int src;
    if (j < 256) {
        src = j;
    } else if (j < 640) {
        int p = j - 256;
        src = 256 + (p & 127) * 3 + (p >> 7);
    } else {
        int p = j - 640;
        src = 640 + (p & 63) * 5 + (p >> 6);
    }
    g_xp[idx] = x[(size_t)n * DIN + src];
}

// ---------------- NormActivation l>0 (in place, planar fp32) ----------------
template <int L>
__global__ void normact_kernel(float* __restrict__ H, int o, int m) {
    int idx = blockIdx.x * 256 + threadIdx.x;
    if (idx >= NROWS * m) return;
    int n = idx / m, v = idx - n * m;
    float* p = H + (size_t)n * DH + o + v;
    float f[L];
    float s2 = 1e-8f;
    #pragma unroll
    for (int i = 0; i < L; i++) { f[i] = p[(size_t)i * m]; s2 += f[i] * f[i]; }
    float nn = sqrtf(s2);
    float sg = 1.0f / (1.0f + expf(-nn));
    float sc = sg / nn;
    #pragma unroll
    for (int i = 0; i < L; i++) p[(size_t)i * m] = f[i] * sc;
}

// ---------------- BatchNorm ----------------
__global__ void bn_zero_kernel() {
    int t = threadIdx.x;
    if (t < 256) g_sum0[t] = 0.0f;
    if (t < 448) g_ssq[t]  = 0.0f;
}

__global__ void bn_reduce_kernel() {
    const int tid = threadIdx.x;
    const int r0  = blockIdx.x * 128;     // 256 blocks * 128 rows
    float s[4] = {0, 0, 0, 0}, q[4] = {0, 0, 0, 0};
    for (int r = 0; r < 128; r++) {
        const float* row = g_outp + (size_t)(r0 + r) * DIN;
        #pragma unroll
        for (int k = 0; k < 4; k++) {
            int j = tid + (k << 8);
            if (j < DIN) {
                float v = row[j];
                s[k] += v;
                q[k] += v * v;
            }
        }
    }
    #pragma unroll
    for (int k = 0; k < 4; k++) {
        int j = tid + (k << 8);
        if (j >= DIN) continue;
        if (j < 256) {
            atomicAdd(&g_sum0[j], s[k]);
            atomicAdd(&g_ssq[j], q[k]);
        } else if (j < 640) {
            atomicAdd(&g_ssq[256 + ((j - 256) & 127)], q[k]);
        } else {
            atomicAdd(&g_ssq[384 + ((j - 640) & 63)], q[k]);
        }
    }
}

__global__ void bn_apply_kernel(const float* __restrict__ bnw,
                                const float* __restrict__ bnb,
                                float* __restrict__ out) {
    int idx = blockIdx.x * 256 + threadIdx.x;
    if (idx >= NROWS * DIN) return;
    int n = idx / DIN, jo = idx - n * DIN;
    const float invN = 1.0f / (float)NROWS;
    float g;
    if (jo < 256) {
        float f   = g_outp[(size_t)n * DIN + jo];
        float mu  = g_sum0[jo] * invN;
        float var = g_ssq[jo] * invN - mu * mu;
        g = (f - mu) * bnw[jo] * rsqrtf(var + 1e-5f) + bnb[jo];
    } else if (jo < 640) {
        int p = jo - 256, v = p / 3, i = p - v * 3;
        float f  = g_outp[(size_t)n * DIN + 256 + (i << 7) + v];
        float n2 = g_ssq[256 + v] * (invN * (1.0f / 3.0f));
        g = f * bnw[256 + v] * rsqrtf(n2 + 1e-5f);
    } else {
        int p = jo - 640, v = p / 5, i = p - v * 5;
        float f  = g_outp[(size_t)n * DIN + 640 + (i << 6) + v];
        float n2 = g_ssq[384 + v] * (invN * (1.0f / 5.0f));
        g = f * bnw[384 + v] * rsqrtf(n2 + 1e-5f);
    }
    out[idx] = g;
}

// ---------------- launch ----------------
#define SMEMSZ (3 * (128 * 20 + 64 * 20) * 4)   // 46080

extern "C" void kernel_launch(void* const* d_in, const int* in_sizes, int n_in,
                              void* d_out, int out_size) {
    const float* x   = (const float*)d_in[0];
    const float* w1  = (const float*)d_in[1];
    const float* w2  = (const float*)d_in[2];
    const float* w3  = (const float*)d_in[3];
    const float* wb  = (const float*)d_in[4];
    const float* bnw = (const float*)d_in[5];
    const float* bnb = (const float*)d_in[6];
    float* out = (float*)d_out;

    cudaFuncSetAttribute(gemm_tf32, cudaFuncAttributeMaxDynamicSharedMemorySize, SMEMSZ);

    float *xp, *h1, *h2, *op, *wt1, *wt2, *wt3, *wtb;
    cudaGetSymbolAddress((void**)&xp,  g_xp);
    cudaGetSymbolAddress((void**)&h1,  g_h1);
    cudaGetSymbolAddress((void**)&h2,  g_h2);
    cudaGetSymbolAddress((void**)&op,  g_outp);
    cudaGetSymbolAddress((void**)&wt1, g_wt1);
    cudaGetSymbolAddress((void**)&wt2, g_wt2);
    cudaGetSymbolAddress((void**)&wt3, g_wt3);
    cudaGetSymbolAddress((void**)&wtb, g_wtb);

    conv_w_all<<<3024, 256>>>(w1, w2, w3, wb, wt1, wt2, wt3, wtb);
    to_planar_kernel<<<(NROWS * DIN) / 256, 256>>>(x);

    auto gemm = [&](const float* A, int lda, size_t sAz, const float* B,
                    float* Cp, int ldc, size_t sCz,
                    int K, int Nout, int nz, int act) {
        dim3 grid(Nout / 64, NROWS / 128, nz);
        gemm_tf32<<<grid, 256, SMEMSZ>>>(
            A, lda, sAz, B, K, K / 16,
            A, lda, sAz, B, K, 0,
            Cp, ldc, sCz, act);
    };
    auto gemm2 = [&](const float* A1p, int lda1, size_t sAz1, const float* B1, int K1,
                     const float* A2p, int lda2, size_t sAz2, const float* B2, int K2,
                     float* Cp, int ldc, size_t sCz, int Nout, int nz) {
        dim3 grid(Nout / 64, NROWS / 128, nz);
        gemm_tf32<<<grid, 256, SMEMSZ>>>(
            A1p, lda1, sAz1, B1, K1, K1 / 16,
            A2p, lda2, sAz2, B2, K2, K2 / 16,
            Cp, ldc, sCz, 0);
    };

    // layer 1: xp -> h1   (l0 gemm fuses scalar NormActivation)
    gemm(xp,        DIN, 0,   wt1,          h1,        DH, 0,   256, 512, 1, 1);
    gemm(xp + 256,  DIN, 128, wt1 + 131072, h1 + 512,  DH, 256, 128, 256, 3, 0);
    gemm(xp + 640,  DIN, 64,  wt1 + 163840, h1 + 1280, DH, 128,  64, 128, 5, 0);

    normact_kernel<3><<<(NROWS * 256) / 256, 256>>>(h1, 512, 256);
    normact_kernel<5><<<(NROWS * 128) / 256, 256>>>(h1, 1280, 128);

    // layer 2: h1 -> h2   (l0 gemm fuses scalar NormActivation)
    gemm(h1,        DH, 0,    wt2,          h2,        DH, 0,   512, 512, 1, 1);
    gemm(h1 + 512,  DH, 256,  wt2 + 262144, h2 + 512,  DH, 256, 256, 256, 3, 0);
    gemm(h1 + 1280, DH, 128,  wt2 + 327680, h2 + 1280, DH, 128, 128, 128, 5, 0);

    normact_kernel<3><<<(NROWS * 256) / 256, 256>>>(h2, 512, 256);
    normact_kernel<5><<<(NROWS * 128) / 256, 256>>>(h2, 1280, 128);

    // layer 3 + skip, fused concat-K: op = h2@W3 + xp@Wb
    gemm2(h2,        DH, 0,   wt3,          512, xp,       DIN, 0,   wtb,         256,
          op,       DIN, 0,   256, 1);
    gemm2(h2 + 512,  DH, 256, wt3 + 131072, 256, xp + 256, DIN, 128, wtb + 65536, 128,
          op + 256, DIN, 128, 128, 3);
    gemm2(h2 + 1280, DH, 128, wt3 + 163840, 128, xp + 640, DIN, 64,  wtb + 81920,  64,
          op + 640, DIN, 64,   64, 5);

    // batch norm -> interleaved fp32 output
    bn_zero_kernel<<<1, 512>>>();
    bn_reduce_kernel<<<256, 256>>>();
    bn_apply_kernel<<<(NROWS * DIN) / 256, 256>>>(bnw, bnb, out);
}

// round 12
// speedup vs baseline: 1.1358x; 1.1319x over previous
#include <cuda_runtime.h>
#include <math.h>
#include <stdint.h>

#define NROWS 32768
#define DIN   960
#define DH    1920

// ---------------- static device buffers (no allocations) ----------------
__device__ float g_xp [(size_t)NROWS * DIN];   // x planar fp32
__device__ float g_h1 [(size_t)NROWS * DH];
__device__ float g_h2 [(size_t)NROWS * DH];
__device__ float g_outp[(size_t)NROWS * DIN];
__device__ float g_sum0[256];
__device__ float g_ssq[448];
__device__ float g_wt1[172032];   // transposed [Nout,K] fp32, alpha folded
__device__ float g_wt2[344064];
__device__ float g_wt3[172032];
__device__ float g_wtb[86016];

// ---------------- helpers ----------------
__device__ __forceinline__ uint32_t s2u(const void* p) {
    uint32_t a;
    asm("{ .reg .u64 t; cvta.to.shared.u64 t, %1; cvt.u32.u64 %0, t; }"
        : "=r"(a) : "l"(p));
    return a;
}

__device__ __forceinline__ void cp16(uint32_t dst, const void* src) {
    asm volatile("cp.async.cg.shared.global [%0], [%1], 16;"
                 :: "r"(dst), "l"(src));
}

__device__ __forceinline__ uint32_t f2tf(float x) {
    uint32_t r;
    asm("cvt.rna.tf32.f32 %0, %1;" : "=r"(r) : "f"(x));
    return r;
}

__device__ __forceinline__ void mma_tf32(float* d, const uint32_t* a,
                                         uint32_t b0, uint32_t b1) {
    asm volatile(
        "mma.sync.aligned.m16n8k8.row.col.f32.tf32.tf32.f32 "
        "{%0,%1,%2,%3}, {%4,%5,%6,%7}, {%8,%9}, {%0,%1,%2,%3};"
        : "+f"(d[0]), "+f"(d[1]), "+f"(d[2]), "+f"(d[3])
        : "r"(a[0]), "r"(a[1]), "r"(a[2]), "r"(a[3]), "r"(b0), "r"(b1));
}

// ---------------- 3xTF32 GEMM, two concatenated operand sets ----------------
// (identical to the 1845us best kernel: R9 config)
template <int BN>
__global__ __launch_bounds__(256, 2) void gemm_tf32(
    const float* __restrict__ A1, int lda1, size_t sAz1,
    const float* __restrict__ B1, int ldb1, int nc1,
    const float* __restrict__ A2, int lda2, size_t sAz2,
    const float* __restrict__ B2, int ldb2, int nc2,
    float* __restrict__ C, int ldc, size_t sCz, int act)
{
    constexpr int WN = (BN == 128) ? 4 : 2;
    constexpr int MT = (BN == 128) ? 4 : 2;
    constexpr int ST = 3;
    extern __shared__ float dsm[];
    float* sAb = dsm;
    float* sBb = dsm + ST * 128 * 20;

    A1 += (size_t)blockIdx.z * sAz1;
    A2 += (size_t)blockIdx.z * sAz2;
    C  += (size_t)blockIdx.z * sCz;

    const int tid = threadIdx.x, wid = tid >> 5, lane = tid & 31;
    const int g = lane >> 2, t = lane & 3;
    const int wm = wid / WN, wn = wid % WN;
    const int row0 = blockIdx.y << 7;
    const int n0   = blockIdx.x * BN;
    const int tot  = nc1 + nc2;

    float acc[MT][4][4] = {};

    auto issue = [&](int cc, int s) {
        if (cc < tot) {
            const float* Asrc; const float* Bsrc; int la, lb;
            if (cc < nc1) {
                Asrc = A1 + (size_t)row0 * lda1 + cc * 16;
                Bsrc = B1 + (size_t)n0 * ldb1 + cc * 16;
                la = lda1; lb = ldb1;
            } else {
                int c2 = cc - nc1;
                Asrc = A2 + (size_t)row0 * lda2 + c2 * 16;
                Bsrc = B2 + (size_t)n0 * ldb2 + c2 * 16;
                la = lda2; lb = ldb2;
            }
            uint32_t da = s2u(sAb + s * (128 * 20));
            #pragma unroll
            for (int i = tid; i < 512; i += 256) {
                int r = i >> 2, u = i & 3;
                cp16(da + r * 80 + u * 16, Asrc + (size_t)r * la + u * 4);
            }
            uint32_t db = s2u(sBb + s * (BN * 20));
            #pragma unroll
            for (int i = tid; i < BN * 4; i += 256) {
                int r = i >> 2, u = i & 3;
                cp16(db + r * 80 + u * 16, Bsrc + (size_t)r * lb + u * 4);
            }
        }
        asm volatile("cp.async.commit_group;");
    };

    issue(0, 0); issue(1, 1); issue(2, 2);

    for (int cc = 0; cc < tot; cc++) {
        asm volatile("cp.async.wait_group 2;");
        __syncthreads();

        const int s = cc % ST;
        const float* a = sAb + s * (128 * 20);
        const float* b = sBb + s * (BN * 20);

        #pragma unroll
        for (int ks = 0; ks < 2; ks++) {
            const int kb = ks * 8;
            uint32_t bhi[4][2], blo[4][2];
            #pragma unroll
            for (int nt = 0; nt < 4; nt++) {
                int nr = wn * 32 + nt * 8 + g;
                float f0 = b[nr * 20 + kb + t];
                float f1 = b[nr * 20 + kb + 4 + t];
                bhi[nt][0] = f2tf(f0);
                blo[nt][0] = f2tf(f0 - __uint_as_float(bhi[nt][0]));
                bhi[nt][1] = f2tf(f1);
                blo[nt][1] = f2tf(f1 - __uint_as_float(bhi[nt][1]));
            }
            #pragma unroll
            for (int mp = 0; mp < MT / 2; mp++) {
                uint32_t ahi[2][4], alo[2][4];
                #pragma unroll
                for (int q = 0; q < 2; q++) {
                    int r0 = wm * (MT * 16) + (mp * 2 + q) * 16 + g;
                    float a0 = a[r0 * 20 + kb + t];
                    float a1 = a[(r0 + 8) * 20 + kb + t];
                    float a2 = a[r0 * 20 + kb + 4 + t];
                    float a3 = a[(r0 + 8) * 20 + kb + 4 + t];
                    ahi[q][0] = f2tf(a0); alo[q][0] = f2tf(a0 - __uint_as_float(ahi[q][0]));
                    ahi[q][1] = f2tf(a1); alo[q][1] = f2tf(a1 - __uint_as_float(ahi[q][1]));
                    ahi[q][2] = f2tf(a2); alo[q][2] = f2tf(a2 - __uint_as_float(ahi[q][2]));
                    ahi[q][3] = f2tf(a3); alo[q][3] = f2tf(a3 - __uint_as_float(ahi[q][3]));
                }
                #pragma unroll
                for (int q = 0; q < 2; q++)
                    #pragma unroll
                    for (int nt = 0; nt < 4; nt++)
                        mma_tf32(acc[mp * 2 + q][nt], ahi[q], bhi[nt][0], bhi[nt][1]);
                #pragma unroll
                for (int q = 0; q < 2; q++)
                    #pragma unroll
                    for (int nt = 0; nt < 4; nt++)
                        mma_tf32(acc[mp * 2 + q][nt], ahi[q], blo[nt][0], blo[nt][1]);
                #pragma unroll
                for (int q = 0; q < 2; q++)
                    #pragma unroll
                    for (int nt = 0; nt < 4; nt++)
                        mma_tf32(acc[mp * 2 + q][nt], alo[q], bhi[nt][0], bhi[nt][1]);
            }
        }
        __syncthreads();
        issue(cc + 3, s);
    }

    const int tig = lane & 3;
    #pragma unroll
    for (int mt = 0; mt < MT; mt++) {
        int r = row0 + wm * (MT * 16) + mt * 16 + g;
        #pragma unroll
        for (int nt = 0; nt < 4; nt++) {
            int cI = n0 + wn * 32 + nt * 8 + tig * 2;
            float v[4] = {acc[mt][nt][0], acc[mt][nt][1],
                          acc[mt][nt][2], acc[mt][nt][3]};
            if (act) {
                #pragma unroll
                for (int q = 0; q < 4; q++) {
                    float nn = sqrtf(v[q] * v[q] + 1e-8f);
                    float sg = 1.0f / (1.0f + expf(-nn));
                    v[q] = v[q] * sg / nn;
                }
            }
            float* p0 = C + (size_t)r * ldc + cI;
            float* p1 = p0 + (size_t)8 * ldc;
            *(float2*)p0 = make_float2(v[0], v[1]);
            *(float2*)p1 = make_float2(v[2], v[3]);
        }
    }
}

// ---------------- fused weight prep: all 12 segments in one launch ----------
__global__ void conv_w_all(const float* __restrict__ w1, const float* __restrict__ w2,
                           const float* __restrict__ w3, const float* __restrict__ wb,
                           float* __restrict__ t1, float* __restrict__ t2,
                           float* __restrict__ t3, float* __restrict__ tb) {
    int idx = blockIdx.x * 256 + threadIdx.x;
    if (idx >= 774144) return;
    const int ends[12] = {131072, 163840, 172032, 434176, 499712, 516096,
                          647168, 679936, 688128, 753664, 770048, 774144};
    const int Ks[12]   = {256, 128, 64, 512, 256, 128, 512, 256, 128, 256, 128, 64};
    const int Ns[12]   = {512, 256, 128, 512, 256, 128, 256, 128, 64, 256, 128, 64};
    int sidx = 0;
    while (idx >= ends[sidx]) sidx++;
    int start = sidx ? ends[sidx - 1] : 0;
    const float* src; float* dst; int tbase;
    if (sidx < 3)      { src = w1; dst = t1; tbase = 0; }
    else if (sidx < 6) { src = w2; dst = t2; tbase = 172032; }
    else if (sidx < 9) { src = w3; dst = t3; tbase = 516096; }
    else               { src = wb; dst = tb; tbase = 688128; }
    int segoff = start - tbase;
    int local  = idx - start;
    int K = Ks[sidx], Nout = Ns[sidx];
    int u = local / Nout, v = local - u * Nout;
    float alpha = 1.0f / sqrtf((float)K);
    dst[segoff + (size_t)v * K + u] = src[segoff + local] * alpha;
}

// ---------------- x interleaved -> planar fp32 ----------------
__global__ void to_planar_kernel(const float* __restrict__ x) {
    int idx = blockIdx.x * 256 + threadIdx.x;
    if (idx >= NROWS * DIN) return;
    int n = idx / DIN, j = idx - n * DIN;
    int src;
    if (j < 256) {
        src = j;
    } else if (j < 640) {
        int p = j - 256;
        src = 256 + (p & 127) * 3 + (p >> 7);
    } else {
        int p = j - 640;
        src = 640 + (p & 63) * 5 + (p >> 6);
    }
    g_xp[idx] = x[(size_t)n * DIN + src];
}

// ---------------- NormActivation l>0 (in place, planar fp32) ----------------
template <int L>
__global__ void normact_kernel(float* __restrict__ H, int o, int m) {
    int idx = blockIdx.x * 256 + threadIdx.x;
    if (idx >= NROWS * m) return;
    int n = idx / m, v = idx - n * m;
    float* p = H + (size_t)n * DH + o + v;
    float f[L];
    float s2 = 1e-8f;
    #pragma unroll
    for (int i = 0; i < L; i++) { f[i] = p[(size_t)i * m]; s2 += f[i] * f[i]; }
    float nn = sqrtf(s2);
    float sg = 1.0f / (1.0f + expf(-nn));
    float sc = sg / nn;
    #pragma unroll
    for (int i = 0; i < L; i++) p[(size_t)i * m] = f[i] * sc;
}

// ---------------- BatchNorm ----------------
__global__ void bn_zero_kernel() {
    int t = threadIdx.x;
    if (t < 256) g_sum0[t] = 0.0f;
    if (t < 448) g_ssq[t]  = 0.0f;
}

__global__ void bn_reduce_kernel() {
    const int tid = threadIdx.x;
    const int r0  = blockIdx.x * 128;
    float s[4] = {0, 0, 0, 0}, q[4] = {0, 0, 0, 0};
    for (int r = 0; r < 128; r++) {
        const float* row = g_outp + (size_t)(r0 + r) * DIN;
        #pragma unroll
        for (int k = 0; k < 4; k++) {
            int j = tid + (k << 8);
            if (j < DIN) {
                float v = row[j];
                s[k] += v;
                q[k] += v * v;
            }
        }
    }
    #pragma unroll
    for (int k = 0; k < 4; k++) {
        int j = tid + (k << 8);
        if (j >= DIN) continue;
        if (j < 256) {
            atomicAdd(&g_sum0[j], s[k]);
            atomicAdd(&g_ssq[j], q[k]);
        } else if (j < 640) {
            atomicAdd(&g_ssq[256 + ((j - 256) & 127)], q[k]);
        } else {
            atomicAdd(&g_ssq[384 + ((j - 640) & 63)], q[k]);
        }
    }
}

__global__ void bn_apply_kernel(const float* __restrict__ bnw,
                                const float* __restrict__ bnb,
                                float* __restrict__ out) {
    int idx = blockIdx.x * 256 + threadIdx.x;
    if (idx >= NROWS * DIN) return;
    int n = idx / DIN, jo = idx - n * DIN;
    const float invN = 1.0f / (float)NROWS;
    float g;
    if (jo < 256) {
        float f   = g_outp[(size_t)n * DIN + jo];
        float mu  = g_sum0[jo] * invN;
        float var = g_ssq[jo] * invN - mu * mu;
        g = (f - mu) * bnw[jo] * rsqrtf(var + 1e-5f) + bnb[jo];
    } else if (jo < 640) {
        int p = jo - 256, v = p / 3, i = p - v * 3;
        float f  = g_outp[(size_t)n * DIN + 256 + (i << 7) + v];
        float n2 = g_ssq[256 + v] * (invN * (1.0f / 3.0f));
        g = f * bnw[256 + v] * rsqrtf(n2 + 1e-5f);
    } else {
        int p = jo - 640, v = p / 5, i = p - v * 5;
        float f  = g_outp[(size_t)n * DIN + 640 + (i << 6) + v];
        float n2 = g_ssq[384 + v] * (invN * (1.0f / 5.0f));
        g = f * bnw[384 + v] * rsqrtf(n2 + 1e-5f);
    }
    out[idx] = g;
}

// ---------------- launch ----------------
#define SMEM128 (3 * (128 * 20 + 128 * 20) * 4)   // 61440
#define SMEM64  (3 * (128 * 20 + 64 * 20) * 4)    // 46080

extern "C" void kernel_launch(void* const* d_in, const int* in_sizes, int n_in,
                              void* d_out, int out_size) {
    const float* x   = (const float*)d_in[0];
    const float* w1  = (const float*)d_in[1];
    const float* w2  = (const float*)d_in[2];
    const float* w3  = (const float*)d_in[3];
    const float* wb  = (const float*)d_in[4];
    const float* bnw = (const float*)d_in[5];
    const float* bnb = (const float*)d_in[6];
    float* out = (float*)d_out;

    // one-time host-side resources (streams/events are not device memory)
    static int inited = 0;
    static cudaStream_t s1, s2, s3;
    static cudaEvent_t e0, eb1, eb2, eb3;
    if (!inited) {
        cudaFuncSetAttribute(gemm_tf32<128>, cudaFuncAttributeMaxDynamicSharedMemorySize, SMEM128);
        cudaFuncSetAttribute(gemm_tf32<64>,  cudaFuncAttributeMaxDynamicSharedMemorySize, SMEM64);
        cudaStreamCreateWithFlags(&s1, cudaStreamNonBlocking);
        cudaStreamCreateWithFlags(&s2, cudaStreamNonBlocking);
        cudaStreamCreateWithFlags(&s3, cudaStreamNonBlocking);
        cudaEventCreateWithFlags(&e0,  cudaEventDisableTiming);
        cudaEventCreateWithFlags(&eb1, cudaEventDisableTiming);
        cudaEventCreateWithFlags(&eb2, cudaEventDisableTiming);
        cudaEventCreateWithFlags(&eb3, cudaEventDisableTiming);
        inited = 1;
    }

    float *xp, *h1, *h2, *op, *wt1, *wt2, *wt3, *wtb;
    cudaGetSymbolAddress((void**)&xp,  g_xp);
    cudaGetSymbolAddress((void**)&h1,  g_h1);
    cudaGetSymbolAddress((void**)&h2,  g_h2);
    cudaGetSymbolAddress((void**)&op,  g_outp);
    cudaGetSymbolAddress((void**)&wt1, g_wt1);
    cudaGetSymbolAddress((void**)&wt2, g_wt2);
    cudaGetSymbolAddress((void**)&wt3, g_wt3);
    cudaGetSymbolAddress((void**)&wtb, g_wtb);

    auto gemm = [&](cudaStream_t st, const float* A, int lda, size_t sAz, const float* B,
                    float* Cp, int ldc, size_t sCz,
                    int K, int Nout, int nz, int act) {
        if (Nout >= 128) {
            dim3 grid(Nout / 128, NROWS / 128, nz);
            gemm_tf32<128><<<grid, 256, SMEM128, st>>>(
                A, lda, sAz, B, K, K / 16, A, lda, sAz, B, K, 0, Cp, ldc, sCz, act);
        } else {
            dim3 grid(Nout / 64, NROWS / 128, nz);
            gemm_tf32<64><<<grid, 256, SMEM64, st>>>(
                A, lda, sAz, B, K, K / 16, A, lda, sAz, B, K, 0, Cp, ldc, sCz, act);
        }
    };
    auto gemm2 = [&](cudaStream_t st,
                     const float* A1p, int lda1, size_t sAz1, const float* B1, int K1,
                     const float* A2p, int lda2, size_t sAz2, const float* B2, int K2,
                     float* Cp, int ldc, size_t sCz, int Nout, int nz) {
        if (Nout >= 128) {
            dim3 grid(Nout / 128, NROWS / 128, nz);
            gemm_tf32<128><<<grid, 256, SMEM128, st>>>(
                A1p, lda1, sAz1, B1, K1, K1 / 16,
                A2p, lda2, sAz2, B2, K2, K2 / 16, Cp, ldc, sCz, 0);
        } else {
            dim3 grid(Nout / 64, NROWS / 128, nz);
            gemm_tf32<64><<<grid, 256, SMEM64, st>>>(
                A1p, lda1, sAz1, B1, K1, K1 / 16,
                A2p, lda2, sAz2, B2, K2, K2 / 16, Cp, ldc, sCz, 0);
        }
    };

    // ---- prologue on the capture (default) stream ----
    conv_w_all<<<3024, 256>>>(w1, w2, w3, wb, wt1, wt2, wt3, wtb);
    to_planar_kernel<<<(NROWS * DIN) / 256, 256>>>(x);
    bn_zero_kernel<<<1, 512>>>();
    cudaEventRecord(e0, 0);

    // ---- fork: three independent irrep chains ----
    cudaStreamWaitEvent(s1, e0, 0);
    cudaStreamWaitEvent(s2, e0, 0);
    cudaStreamWaitEvent(s3, e0, 0);

    // l0 chain (s1): L1 -> L2 -> L3+skip  (scalar normact fused into gemm epilogues)
    gemm(s1, xp, DIN, 0, wt1, h1, DH, 0, 256, 512, 1, 1);
    gemm(s1, h1, DH, 0, wt2, h2, DH, 0, 512, 512, 1, 1);
    gemm2(s1, h2, DH, 0, wt3, 512, xp, DIN, 0, wtb, 256, op, DIN, 0, 256, 1);
    cudaEventRecord(eb1, s1);

    // l1 chain (s2)
    gemm(s2, xp + 256, DIN, 128, wt1 + 131072, h1 + 512, DH, 256, 128, 256, 3, 0);
    normact_kernel<3><<<(NROWS * 256) / 256, 256, 0, s2>>>(h1, 512, 256);
    gemm(s2, h1 + 512, DH, 256, wt2 + 262144, h2 + 512, DH, 256, 256, 256, 3, 0);
    normact_kernel<3><<<(NROWS * 256) / 256, 256, 0, s2>>>(h2, 512, 256);
    gemm2(s2, h2 + 512, DH, 256, wt3 + 131072, 256,
          xp + 256, DIN, 128, wtb + 65536, 128, op + 256, DIN, 128, 128, 3);
    cudaEventRecord(eb2, s2);

    // l2 chain (s3)
    gemm(s3, xp + 640, DIN, 64, wt1 + 163840, h1 + 1280, DH, 128, 64, 128, 5, 0);
    normact_kernel<5><<<(NROWS * 128) / 256, 256, 0, s3>>>(h1, 1280, 128);
    gemm(s3, h1 + 1280, DH, 128, wt2 + 327680, h2 + 1280, DH, 128, 128, 128, 5, 0);
    normact_kernel<5><<<(NROWS * 128) / 256, 256, 0, s3>>>(h2, 1280, 128);
    gemm2(s3, h2 + 1280, DH, 128, wt3 + 163840, 128,
          xp + 640, DIN, 64, wtb + 81920, 64, op + 640, DIN, 64, 64, 5);
    cudaEventRecord(eb3, s3);

    // ---- join, then batch norm on the capture stream ----
    cudaStreamWaitEvent(0, eb1, 0);
    cudaStreamWaitEvent(0, eb2, 0);
    cudaStreamWaitEvent(0, eb3, 0);
    bn_reduce_kernel<<<256, 256>>>();
    bn_apply_kernel<<<(NROWS * DIN) / 256, 256>>>(bnw, bnb, out);
}

// round 13
// speedup vs baseline: 1.5405x; 1.3564x over previous
#include <cuda_runtime.h>
#include <cuda_fp16.h>
#include <math.h>
#include <stdint.h>

#define NROWS 32768
#define DIN   960
#define DH    1920

// ---------------- static device buffers (no allocations) ----------------
__device__ __half g_xph[(size_t)NROWS * DIN];
__device__ __half g_xpl[(size_t)NROWS * DIN];
__device__ float  g_h1 [(size_t)NROWS * DH];    // pre-normact fp32 (l>0 cols)
__device__ __half g_h1h[(size_t)NROWS * DH];
__device__ __half g_h1l[(size_t)NROWS * DH];
__device__ float  g_h2 [(size_t)NROWS * DH];
__device__ __half g_h2h[(size_t)NROWS * DH];
__device__ __half g_h2l[(size_t)NROWS * DH];
__device__ float  g_outp[(size_t)NROWS * DIN];
__device__ float  g_sum0[256];
__device__ float  g_ssq[448];
__device__ __half g_wt1h[172032], g_wt1l[172032];
__device__ __half g_wt2h[344064], g_wt2l[344064];
__device__ __half g_wt3h[172032], g_wt3l[172032];
__device__ __half g_wtbh[86016],  g_wtbl[86016];

// ---------------- helpers ----------------
__device__ __forceinline__ uint32_t s2u(const void* p) {
    uint32_t a;
    asm("{ .reg .u64 t; cvta.to.shared.u64 t, %1; cvt.u32.u64 %0, t; }"
        : "=r"(a) : "l"(p));
    return a;
}

__device__ __forceinline__ void cp16(uint32_t dst, const void* src) {
    asm volatile("cp.async.cg.shared.global [%0], [%1], 16;"
                 :: "r"(dst), "l"(src));
}

__device__ __forceinline__ void ldmx4(uint32_t* r, uint32_t addr) {
    asm volatile("ldmatrix.sync.aligned.m8n8.x4.shared.b16 {%0,%1,%2,%3}, [%4];"
                 : "=r"(r[0]), "=r"(r[1]), "=r"(r[2]), "=r"(r[3]) : "r"(addr));
}

__device__ __forceinline__ void mma_f16(float* d, const uint32_t* a,
                                        uint32_t b0, uint32_t b1) {
    asm volatile(
        "mma.sync.aligned.m16n8k16.row.col.f32.f16.f16.f32 "
        "{%0,%1,%2,%3}, {%4,%5,%6,%7}, {%8,%9}, {%0,%1,%2,%3};"
        : "+f"(d[0]), "+f"(d[1]), "+f"(d[2]), "+f"(d[3])
        : "r"(a[0]), "r"(a[1]), "r"(a[2]), "r"(a[3]), "r"(b0), "r"(b1));
}

// ---------------- 3xFP16 GEMM (hi/lo split; hh+hl+lh), two operand sets ----
// C[M,Nout] = A1@B1^T + A2@B2^T, fp32 accumulate. A/B pre-split half planes.
// smem row layout: [hi 16 halves | lo 16 halves | pad], pitch 80 B.
// BM=128, BN=128/64, BK=16, 256 threads, 3-stage cp.async, ldmatrix frags.
// act=1: l=0 NormActivation in epilogue, writes half hi/lo planes Ch/Cl.
template <int BN>
__global__ __launch_bounds__(256, 2) void gemm_f16(
    const __half* __restrict__ A1h, const __half* __restrict__ A1l, int lda1, size_t sAz1,
    const __half* __restrict__ B1h, const __half* __restrict__ B1l, int ldb1, int nc1,
    const __half* __restrict__ A2h, const __half* __restrict__ A2l, int lda2, size_t sAz2,
    const __half* __restrict__ B2h, const __half* __restrict__ B2l, int ldb2, int nc2,
    float* __restrict__ C, __half* __restrict__ Ch, __half* __restrict__ Cl,
    int ldc, size_t sCz, int act)
{
    constexpr int WN = (BN == 128) ? 4 : 2;
    constexpr int MT = (BN == 128) ? 4 : 2;
    constexpr int ST = 3;
    extern __shared__ char dsm[];
    char* sAb = dsm;                        // [ST][128*80]
    char* sBb = dsm + ST * 128 * 80;        // [ST][BN*80]

    A1h += (size_t)blockIdx.z * sAz1;  A1l += (size_t)blockIdx.z * sAz1;
    A2h += (size_t)blockIdx.z * sAz2;  A2l += (size_t)blockIdx.z * sAz2;
    C   += (size_t)blockIdx.z * sCz;
    Ch  += (size_t)blockIdx.z * sCz;
    Cl  += (size_t)blockIdx.z * sCz;

    const int tid = threadIdx.x, wid = tid >> 5, lane = tid & 31;
    const int g = lane >> 2, tig = lane & 3;
    const int wm = wid / WN, wn = wid % WN;
    const int row0 = blockIdx.y << 7;
    const int n0   = blockIdx.x * BN;
    const int tot  = nc1 + nc2;

    float acc[MT][4][4] = {};

    auto issue = [&](int cc, int s) {
        if (cc < tot) {
            const __half *Ah, *Al, *Bh, *Bl; int la, lb;
            if (cc < nc1) {
                Ah = A1h + (size_t)row0 * lda1 + cc * 16;
                Al = A1l + (size_t)row0 * lda1 + cc * 16;
                Bh = B1h + (size_t)n0 * ldb1 + cc * 16;
                Bl = B1l + (size_t)n0 * ldb1 + cc * 16;
                la = lda1; lb = ldb1;
            } else {
                int c2 = cc - nc1;
                Ah = A2h + (size_t)row0 * lda2 + c2 * 16;
                Al = A2l + (size_t)row0 * lda2 + c2 * 16;
                Bh = B2h + (size_t)n0 * ldb2 + c2 * 16;
                Bl = B2l + (size_t)n0 * ldb2 + c2 * 16;
                la = lda2; lb = ldb2;
            }
            uint32_t da = s2u(sAb + s * (128 * 80));
            #pragma unroll
            for (int i = tid; i < 512; i += 256) {
                int r = i >> 2, u = i & 3;
                const __half* src = ((u & 2) ? Al : Ah) + (size_t)r * la + (u & 1) * 8;
                cp16(da + r * 80 + u * 16, src);
            }
            uint32_t db = s2u(sBb + s * (BN * 80));
            #pragma unroll
            for (int i = tid; i < BN * 4; i += 256) {
                int r = i >> 2, u = i & 3;
                const __half* src = ((u & 2) ? Bl : Bh) + (size_t)r * lb + (u & 1) * 8;
                cp16(db + r * 80 + u * 16, src);
            }
        }
        asm volatile("cp.async.commit_group;");
    };

    issue(0, 0); issue(1, 1); issue(2, 2);

    for (int cc = 0; cc < tot; cc++) {
        asm volatile("cp.async.wait_group 2;");
        __syncthreads();

        const int s = cc % ST;
        uint32_t aBase = s2u(sAb + s * (128 * 80));
        uint32_t bBase = s2u(sBb + s * (BN * 80));

        #pragma unroll
        for (int ntp = 0; ntp < 2; ntp++) {
            // B frags for two n8 tiles: {b0(nt0), b1(nt0), b0(nt1), b1(nt1)}
            uint32_t bh[4], bl[4];
            uint32_t baddr = bBase
                + (wn * 32 + ntp * 16 + (lane & 7) + ((lane & 16) >> 1)) * 80
                + ((lane & 8) << 1);
            ldmx4(bh, baddr);
            ldmx4(bl, baddr + 32);
            #pragma unroll
            for (int mp = 0; mp < MT / 2; mp++) {
                uint32_t ah[2][4], al[2][4];
                #pragma unroll
                for (int q = 0; q < 2; q++) {
                    int rb = wm * (MT * 16) + (mp * 2 + q) * 16;
                    uint32_t aaddr = aBase + (rb + (lane & 15)) * 80 + (lane & 16);
                    ldmx4(ah[q], aaddr);
                    ldmx4(al[q], aaddr + 32);
                }
                // per-accumulator order: hh -> hl -> lh
                #pragma unroll
                for (int q = 0; q < 2; q++)
                    #pragma unroll
                    for (int n2 = 0; n2 < 2; n2++)
                        mma_f16(acc[mp * 2 + q][ntp * 2 + n2], ah[q],
                                bh[n2 * 2], bh[n2 * 2 + 1]);
                #pragma unroll
                for (int q = 0; q < 2; q++)
                    #pragma unroll
                    for (int n2 = 0; n2 < 2; n2++)
                        mma_f16(acc[mp * 2 + q][ntp * 2 + n2], ah[q],
                                bl[n2 * 2], bl[n2 * 2 + 1]);
                #pragma unroll
                for (int q = 0; q < 2; q++)
                    #pragma unroll
                    for (int n2 = 0; n2 < 2; n2++)
                        mma_f16(acc[mp * 2 + q][ntp * 2 + n2], al[q],
                                bh[n2 * 2], bh[n2 * 2 + 1]);
            }
        }
        __syncthreads();
        issue(cc + 3, s);
    }

    // epilogue
    #pragma unroll
    for (int mt = 0; mt < MT; mt++) {
        int r = row0 + wm * (MT * 16) + mt * 16 + g;
        #pragma unroll
        for (int nt = 0; nt < 4; nt++) {
            int cI = n0 + wn * 32 + nt * 8 + tig * 2;
            float v[4] = {acc[mt][nt][0], acc[mt][nt][1],
                          acc[mt][nt][2], acc[mt][nt][3]};
            size_t o0 = (size_t)r * ldc + cI;
            size_t o1 = o0 + (size_t)8 * ldc;
            if (act) {
                __half hh[4], hl[4];
                #pragma unroll
                for (int q = 0; q < 4; q++) {
                    float nn = sqrtf(v[q] * v[q] + 1e-8f);
                    float sg = 1.0f / (1.0f + expf(-nn));
                    float rr = v[q] * sg / nn;
                    hh[q] = __float2half_rn(rr);
                    hl[q] = __float2half_rn(rr - __half2float(hh[q]));
                }
                *(__half2*)(Ch + o0) = __halves2half2(hh[0], hh[1]);
                *(__half2*)(Ch + o1) = __halves2half2(hh[2], hh[3]);
                *(__half2*)(Cl + o0) = __halves2half2(hl[0], hl[1]);
                *(__half2*)(Cl + o1) = __halves2half2(hl[2], hl[3]);
            } else {
                *(float2*)(C + o0) = make_float2(v[0], v[1]);
                *(float2*)(C + o1) = make_float2(v[2], v[3]);
            }
        }
    }
}

// ---------------- fused weight prep: 12 segments, transposed, fp16 hi/lo ---
__global__ void conv_w_all(const float* __restrict__ w1, const float* __restrict__ w2,
                           const float* __restrict__ w3, const float* __restrict__ wb,
                           __half* __restrict__ t1h, __half* __restrict__ t1l,
                           __half* __restrict__ t2h, __half* __restrict__ t2l,
                           __half* __restrict__ t3h, __half* __restrict__ t3l,
                           __half* __restrict__ tbh, __half* __restrict__ tbl) {
    int idx = blockIdx.x * 256 + threadIdx.x;
    if (idx >= 774144) return;
    const int ends[12] = {131072, 163840, 172032, 434176, 499712, 516096,
                          647168, 679936, 688128, 753664, 770048, 774144};
    const int Ks[12]   = {256, 128, 64, 512, 256, 128, 512, 256, 128, 256, 128, 64};
    const int Ns[12]   = {512, 256, 128, 512, 256, 128, 256, 128, 64, 256, 128, 64};
    int sidx = 0;
    while (idx >= ends[sidx]) sidx++;
    int start = sidx ? ends[sidx - 1] : 0;
    const float* src; __half *dh, *dl; int tbase;
    if (sidx < 3)      { src = w1; dh = t1h; dl = t1l; tbase = 0; }
    else if (sidx < 6) { src = w2; dh = t2h; dl = t2l; tbase = 172032; }
    else if (sidx < 9) { src = w3; dh = t3h; dl = t3l; tbase = 516096; }
    else               { src = wb; dh = tbh; dl = tbl; tbase = 688128; }
    int segoff = start - tbase;
    int local  = idx - start;
    int K = Ks[sidx], Nout = Ns[sidx];
    int u = local / Nout, v = local - u * Nout;
    float val = src[segoff + local] * (1.0f / sqrtf((float)K));
    __half hi = __float2half_rn(val);
    size_t o = segoff + (size_t)v * K + u;
    dh[o] = hi;
    dl[o] = __float2half_rn(val - __half2float(hi));
}

// ---------------- x interleaved -> planar fp16 hi/lo ----------------
__global__ void to_planar_kernel(const float* __restrict__ x) {
    int idx = blockIdx.x * 256 + threadIdx.x;
    if (idx >= NROWS * DIN) return;
    int n = idx / DIN, j = idx - n * DIN;
    int src;
    if (j < 256) {
        src = j;
    } else if (j < 640) {
        int p = j - 256;
        src = 256 + (p & 127) * 3 + (p >> 7);
    } else {
        int p = j - 640;
        src = 640 + (p & 63) * 5 + (p >> 6);
    }
    float v = x[(size_t)n * DIN + src];
    __half hi = __float2half_rn(v);
    g_xph[idx] = hi;
    g_xpl[idx] = __float2half_rn(v - __half2float(hi));
}

// ---------------- NormActivation l>0: fp32 in -> fp16 hi/lo planes out -----
template <int L>
__global__ void normact_kernel(const float* __restrict__ H,
                               __half* __restrict__ Hh, __half* __restrict__ Hl,
                               int o, int m) {
    int idx = blockIdx.x * 256 + threadIdx.x;
    if (idx >= NROWS * m) return;
    int n = idx / m, v = idx - n * m;
    const float* p = H + (size_t)n * DH + o + v;
    float f[L];
    float s2 = 1e-8f;
    #pragma unroll
    for (int i = 0; i < L; i++) { f[i] = p[(size_t)i * m]; s2 += f[i] * f[i]; }
    float nn = sqrtf(s2);
    float sg = 1.0f / (1.0f + expf(-nn));
    float sc = sg / nn;
    #pragma unroll
    for (int i = 0; i < L; i++) {
        float r = f[i] * sc;
        __half hi = __float2half_rn(r);
        size_t off = (size_t)n * DH + o + (size_t)i * m + v;
        Hh[off] = hi;
        Hl[off] = __float2half_rn(r - __half2float(hi));
    }
}

// ---------------- BatchNorm ----------------
__global__ void bn_zero_kernel() {
    int t = threadIdx.x;
    if (t < 256) g_sum0[t] = 0.0f;
    if (t < 448) g_ssq[t]  = 0.0f;
}

__global__ void bn_reduce_kernel() {
    const int tid = threadIdx.x;
    const int r0  = blockIdx.x * 128;
    float s[4] = {0, 0, 0, 0}, q[4] = {0, 0, 0, 0};
    for (int r = 0; r < 128; r++) {
        const float* row = g_outp + (size_t)(r0 + r) * DIN;
        #pragma unroll
        for (int k = 0; k < 4; k++) {
            int j = tid + (k << 8);
            if (j < DIN) {
                float v = row[j];
                s[k] += v;
                q[k] += v * v;
            }
        }
    }
    #pragma unroll
    for (int k = 0; k < 4; k++) {
        int j = tid + (k << 8);
        if (j >= DIN) continue;
        if (j < 256) {
            atomicAdd(&g_sum0[j], s[k]);
            atomicAdd(&g_ssq[j], q[k]);
        } else if (j < 640) {
            atomicAdd(&g_ssq[256 + ((j - 256) & 127)], q[k]);
        } else {
            atomicAdd(&g_ssq[384 + ((j - 640) & 63)], q[k]);
        }
    }
}

__global__ void bn_apply_kernel(const float* __restrict__ bnw,
                                const float* __restrict__ bnb,
                                float* __restrict__ out) {
    int idx = blockIdx.x * 256 + threadIdx.x;
    if (idx >= NROWS * DIN) return;
    int n = idx / DIN, jo = idx - n * DIN;
    const float invN = 1.0f / (float)NROWS;
    float g;
    if (jo < 256) {
        float f   = g_outp[(size_t)n * DIN + jo];
        float mu  = g_sum0[jo] * invN;
        float var = g_ssq[jo] * invN - mu * mu;
        g = (f - mu) * bnw[jo] * rsqrtf(var + 1e-5f) + bnb[jo];
    } else if (jo < 640) {
        int p = jo - 256, v = p / 3, i = p - v * 3;
        float f  = g_outp[(size_t)n * DIN + 256 + (i << 7) + v];
        float n2 = g_ssq[256 + v] * (invN * (1.0f / 3.0f));
        g = f * bnw[256 + v] * rsqrtf(n2 + 1e-5f);
    } else {
        int p = jo - 640, v = p / 5, i = p - v * 5;
        float f  = g_outp[(size_t)n * DIN + 640 + (i << 6) + v];
        float n2 = g_ssq[384 + v] * (invN * (1.0f / 5.0f));
        g = f * bnw[384 + v] * rsqrtf(n2 + 1e-5f);
    }
    out[idx] = g;
}

// ---------------- launch ----------------
#define SMEM128 (3 * (128 * 80 + 128 * 80))   // 61440
#define SMEM64  (3 * (128 * 80 + 64 * 80))    // 46080

extern "C" void kernel_launch(void* const* d_in, const int* in_sizes, int n_in,
                              void* d_out, int out_size) {
    const float* x   = (const float*)d_in[0];
    const float* w1  = (const float*)d_in[1];
    const float* w2  = (const float*)d_in[2];
    const float* w3  = (const float*)d_in[3];
    const float* wb  = (const float*)d_in[4];
    const float* bnw = (const float*)d_in[5];
    const float* bnb = (const float*)d_in[6];
    float* out = (float*)d_out;

    static int inited = 0;
    static cudaStream_t s1, s2, s3;
    static cudaEvent_t e0, eb1, eb2, eb3;
    if (!inited) {
        cudaFuncSetAttribute(gemm_f16<128>, cudaFuncAttributeMaxDynamicSharedMemorySize, SMEM128);
        cudaFuncSetAttribute(gemm_f16<64>,  cudaFuncAttributeMaxDynamicSharedMemorySize, SMEM64);
        cudaStreamCreateWithFlags(&s1, cudaStreamNonBlocking);
        cudaStreamCreateWithFlags(&s2, cudaStreamNonBlocking);
        cudaStreamCreateWithFlags(&s3, cudaStreamNonBlocking);
        cudaEventCreateWithFlags(&e0,  cudaEventDisableTiming);
        cudaEventCreateWithFlags(&eb1, cudaEventDisableTiming);
        cudaEventCreateWithFlags(&eb2, cudaEventDisableTiming);
        cudaEventCreateWithFlags(&eb3, cudaEventDisableTiming);
        inited = 1;
    }

    __half *xph, *xpl, *h1h, *h1l, *h2h, *h2l;
    __half *w1h, *w1l, *w2h, *w2l, *w3h, *w3l, *wbh, *wbl;
    float *h1, *h2, *op;
    cudaGetSymbolAddress((void**)&xph, g_xph);
    cudaGetSymbolAddress((void**)&xpl, g_xpl);
    cudaGetSymbolAddress((void**)&h1,  g_h1);
    cudaGetSymbolAddress((void**)&h1h, g_h1h);
    cudaGetSymbolAddress((void**)&h1l, g_h1l);
    cudaGetSymbolAddress((void**)&h2,  g_h2);
    cudaGetSymbolAddress((void**)&h2h, g_h2h);
    cudaGetSymbolAddress((void**)&h2l, g_h2l);
    cudaGetSymbolAddress((void**)&op,  g_outp);
    cudaGetSymbolAddress((void**)&w1h, g_wt1h);
    cudaGetSymbolAddress((void**)&w1l, g_wt1l);
    cudaGetSymbolAddress((void**)&w2h, g_wt2h);
    cudaGetSymbolAddress((void**)&w2l, g_wt2l);
    cudaGetSymbolAddress((void**)&w3h, g_wt3h);
    cudaGetSymbolAddress((void**)&w3l, g_wt3l);
    cudaGetSymbolAddress((void**)&wbh, g_wtbh);
    cudaGetSymbolAddress((void**)&wbl, g_wtbl);

    // gemm on pre-split half planes; Cf used when act=0, Ch/Cl when act=1
    auto gemm = [&](cudaStream_t st,
                    const __half* Ah, const __half* Al, int lda, size_t sAz,
                    const __half* Bh, const __half* Bl,
                    float* Cf, __half* Chp, __half* Clp, int ldc, size_t sCz,
                    int K, int Nout, int nz, int act) {
        if (Nout >= 128) {
            dim3 grid(Nout / 128, NROWS / 128, nz);
            gemm_f16<128><<<grid, 256, SMEM128, st>>>(
                Ah, Al, lda, sAz, Bh, Bl, K, K / 16,
                Ah, Al, lda, sAz, Bh, Bl, K, 0,
                Cf, Chp, Clp, ldc, sCz, act);
        } else {
            dim3 grid(Nout / 64, NROWS / 128, nz);
            gemm_f16<64><<<grid, 256, SMEM64, st>>>(
                Ah, Al, lda, sAz, Bh, Bl, K, K / 16,
                Ah, Al, lda, sAz, Bh, Bl, K, 0,
                Cf, Chp, Clp, ldc, sCz, act);
        }
    };
    auto gemm2 = [&](cudaStream_t st,
                     const __half* A1hp, const __half* A1lp, int lda1, size_t sAz1,
                     const __half* B1hp, const __half* B1lp, int K1,
                     const __half* A2hp, const __half* A2lp, int lda2, size_t sAz2,
                     const __half* B2hp, const __half* B2lp, int K2,
                     float* Cf, int ldc, size_t sCz, int Nout, int nz) {
        if (Nout >= 128) {
            dim3 grid(Nout / 128, NROWS / 128, nz);
            gemm_f16<128><<<grid, 256, SMEM128, st>>>(
                A1hp, A1lp, lda1, sAz1, B1hp, B1lp, K1, K1 / 16,
                A2hp, A2lp, lda2, sAz2, B2hp, B2lp, K2, K2 / 16,
                Cf, (__half*)Cf, (__half*)Cf, ldc, sCz, 0);
        } else {
            dim3 grid(Nout / 64, NROWS / 128, nz);
            gemm_f16<64><<<grid, 256, SMEM64, st>>>(
                A1hp, A1lp, lda1, sAz1, B1hp, B1lp, K1, K1 / 16,
                A2hp, A2lp, lda2, sAz2, B2hp, B2lp, K2, K2 / 16,
                Cf, (__half*)Cf, (__half*)Cf, ldc, sCz, 0);
        }
    };

    // ---- prologue on the capture stream ----
    conv_w_all<<<3024, 256>>>(w1, w2, w3, wb, w1h, w1l, w2h, w2l, w3h, w3l, wbh, wbl);
    to_planar_kernel<<<(NROWS * DIN) / 256, 256>>>(x);
    bn_zero_kernel<<<1, 512>>>();
    cudaEventRecord(e0, 0);

    cudaStreamWaitEvent(s1, e0, 0);
    cudaStreamWaitEvent(s2, e0, 0);
    cudaStreamWaitEvent(s3, e0, 0);

    // l0 chain (s1): scalar normact fused into epilogues (writes half planes)
    gemm(s1, xph, xpl, DIN, 0, w1h, w1l, 0, h1h, h1l, DH, 0, 256, 512, 1, 1);
    gemm(s1, h1h, h1l, DH, 0, w2h, w2l, 0, h2h, h2l, DH, 0, 512, 512, 1, 1);
    gemm2(s1, h2h, h2l, DH, 0, w3h, w3l, 512,
          xph, xpl, DIN, 0, wbh, wbl, 256, op, DIN, 0, 256, 1);
    cudaEventRecord(eb1, s1);

    // l1 chain (s2)
    gemm(s2, xph + 256, xpl + 256, DIN, 128, w1h + 131072, w1l + 131072,
         h1 + 512, 0, 0, DH, 256, 128, 256, 3, 0);
    normact_kernel<3><<<(NROWS * 256) / 256, 256, 0, s2>>>(h1, h1h, h1l, 512, 256);
    gemm(s2, h1h + 512, h1l + 512, DH, 256, w2h + 262144, w2l + 262144,
         h2 + 512, 0, 0, DH, 256, 256, 256, 3, 0);
    normact_kernel<3><<<(NROWS * 256) / 256, 256, 0, s2>>>(h2, h2h, h2l, 512, 256);
    gemm2(s2, h2h + 512, h2l + 512, DH, 256, w3h + 131072, w3l + 131072, 256,
          xph + 256, xpl + 256, DIN, 128, wbh + 65536, wbl + 65536, 128,
          op + 256, DIN, 128, 128, 3);
    cudaEventRecord(eb2, s2);

    // l2 chain (s3)
    gemm(s3, xph + 640, xpl + 640, DIN, 64, w1h + 163840, w1l + 163840,
         h1 + 1280, 0, 0, DH, 128, 64, 128, 5, 0);
    normact_kernel<5><<<(NROWS * 128) / 256, 256, 0, s3>>>(h1, h1h, h1l, 1280, 128);
    gemm(s3, h1h + 1280, h1l + 1280, DH, 128, w2h + 327680, w2l + 327680,
         h2 + 1280, 0, 0, DH, 128, 128, 128, 5, 0);
    normact_kernel<5><<<(NROWS * 128) / 256, 256, 0, s3>>>(h2, h2h, h2l, 1280, 128);
    gemm2(s3, h2h + 1280, h2l + 1280, DH, 128, w3h + 163840, w3l + 163840, 128,
          xph + 640, xpl + 640, DIN, 64, wbh + 81920, wbl + 81920, 64,
          op + 640, DIN, 64, 64, 5);
    cudaEventRecord(eb3, s3);

    // ---- join, then batch norm ----
    cudaStreamWaitEvent(0, eb1, 0);
    cudaStreamWaitEvent(0, eb2, 0);
    cudaStreamWaitEvent(0, eb3, 0);
    bn_reduce_kernel<<<256, 256>>>();
    bn_apply_kernel<<<(NROWS * DIN) / 256, 256>>>(bnw, bnb, out);
}

// round 14
// speedup vs baseline: 1.7645x; 1.1453x over previous
#include <cuda_runtime.h>
#include <cuda_fp16.h>
#include <math.h>
#include <stdint.h>

#define NROWS 32768
#define DIN   960
#define DH    1920

// ---------------- static device buffers (no allocations) ----------------
__device__ __half g_xph[(size_t)NROWS * DIN];
__device__ __half g_xpl[(size_t)NROWS * DIN];
__device__ float  g_h1 [(size_t)NROWS * DH];    // pre-normact fp32 (l>0 cols)
__device__ __half g_h1h[(size_t)NROWS * DH];
__device__ __half g_h1l[(size_t)NROWS * DH];
__device__ float  g_h2 [(size_t)NROWS * DH];
__device__ __half g_h2h[(size_t)NROWS * DH];
__device__ __half g_h2l[(size_t)NROWS * DH];
__device__ float  g_outp[(size_t)NROWS * DIN];
__device__ float  g_sum0[256];
__device__ float  g_ssq[448];
__device__ __half g_wt1h[172032], g_wt1l[172032];
__device__ __half g_wt2h[344064], g_wt2l[344064];
__device__ __half g_wt3h[172032], g_wt3l[172032];
__device__ __half g_wtbh[86016],  g_wtbl[86016];

// ---------------- helpers ----------------
__device__ __forceinline__ uint32_t s2u(const void* p) {
    uint32_t a;
    asm("{ .reg .u64 t; cvta.to.shared.u64 t, %1; cvt.u32.u64 %0, t; }"
        : "=r"(a) : "l"(p));
    return a;
}

__device__ __forceinline__ void cp16(uint32_t dst, const void* src) {
    asm volatile("cp.async.cg.shared.global [%0], [%1], 16;"
                 :: "r"(dst), "l"(src));
}

__device__ __forceinline__ void ldmx4(uint32_t* r, uint32_t addr) {
    asm volatile("ldmatrix.sync.aligned.m8n8.x4.shared.b16 {%0,%1,%2,%3}, [%4];"
                 : "=r"(r[0]), "=r"(r[1]), "=r"(r[2]), "=r"(r[3]) : "r"(addr));
}

__device__ __forceinline__ void mma_f16(float* d, const uint32_t* a,
                                        uint32_t b0, uint32_t b1) {
    asm volatile(
        "mma.sync.aligned.m16n8k16.row.col.f32.f16.f16.f32 "
        "{%0,%1,%2,%3}, {%4,%5,%6,%7}, {%8,%9}, {%0,%1,%2,%3};"
        : "+f"(d[0]), "+f"(d[1]), "+f"(d[2]), "+f"(d[3])
        : "r"(a[0]), "r"(a[1]), "r"(a[2]), "r"(a[3]), "r"(b0), "r"(b1));
}

// ---------------- 3xFP16 GEMM (hi/lo split; hh+hl+lh), two operand sets ----
// C[M,Nout] = A1@B1^T + A2@B2^T, fp32 accumulate. A/B pre-split half planes.
// BK=32 per stage. smem row: 8x16B units [hi k0..31 | lo k0..31], pitch 128B,
// XOR swizzle: phys_unit = u ^ (row&7) (conflict-free stores + ldmatrix).
// BM=128, BN=128/64, 256 threads, 3-stage cp.async.
// act=1: l=0 NormActivation in epilogue, writes half hi/lo planes Ch/Cl.
template <int BN>
__global__ __launch_bounds__(256, 2) void gemm_f16(
    const __half* __restrict__ A1h, const __half* __restrict__ A1l, int lda1, size_t sAz1,
    const __half* __restrict__ B1h, const __half* __restrict__ B1l, int ldb1, int nc1,
    const __half* __restrict__ A2h, const __half* __restrict__ A2l, int lda2, size_t sAz2,
    const __half* __restrict__ B2h, const __half* __restrict__ B2l, int ldb2, int nc2,
    float* __restrict__ C, __half* __restrict__ Ch, __half* __restrict__ Cl,
    int ldc, size_t sCz, int act)
{
    constexpr int WN = (BN == 128) ? 4 : 2;
    constexpr int MT = (BN == 128) ? 4 : 2;
    constexpr int ST = 3;
    constexpr int ASTG = 128 * 128;          // bytes per A stage
    constexpr int BSTG = BN * 128;
    extern __shared__ char dsm[];
    char* sAb = dsm;                         // [ST][ASTG]
    char* sBb = dsm + ST * ASTG;             // [ST][BSTG]

    A1h += (size_t)blockIdx.z * sAz1;  A1l += (size_t)blockIdx.z * sAz1;
    A2h += (size_t)blockIdx.z * sAz2;  A2l += (size_t)blockIdx.z * sAz2;
    C   += (size_t)blockIdx.z * sCz;
    Ch  += (size_t)blockIdx.z * sCz;
    Cl  += (size_t)blockIdx.z * sCz;

    const int tid = threadIdx.x, wid = tid >> 5, lane = tid & 31;
    const int g = lane >> 2, tig = lane & 3;
    const int wm = wid / WN, wn = wid % WN;
    const int row0 = blockIdx.y << 7;
    const int n0   = blockIdx.x * BN;
    const int tot  = nc1 + nc2;

    float acc[MT][4][4] = {};

    auto issue = [&](int cc, int s) {
        if (cc < tot) {
            const __half *Ah, *Al, *Bh, *Bl; int la, lb;
            if (cc < nc1) {
                Ah = A1h + (size_t)row0 * lda1 + cc * 32;
                Al = A1l + (size_t)row0 * lda1 + cc * 32;
                Bh = B1h + (size_t)n0 * ldb1 + cc * 32;
                Bl = B1l + (size_t)n0 * ldb1 + cc * 32;
                la = lda1; lb = ldb1;
            } else {
                int c2 = cc - nc1;
                Ah = A2h + (size_t)row0 * lda2 + c2 * 32;
                Al = A2l + (size_t)row0 * lda2 + c2 * 32;
                Bh = B2h + (size_t)n0 * ldb2 + c2 * 32;
                Bl = B2l + (size_t)n0 * ldb2 + c2 * 32;
                la = lda2; lb = ldb2;
            }
            uint32_t da = s2u(sAb + s * ASTG);
            #pragma unroll
            for (int i = tid; i < 1024; i += 256) {
                int r = i >> 3, u = i & 7;
                const __half* src = ((u & 4) ? Al : Ah) + (size_t)r * la + (u & 3) * 8;
                cp16(da + r * 128 + ((u ^ (r & 7)) << 4), src);
            }
            uint32_t db = s2u(sBb + s * BSTG);
            #pragma unroll
            for (int i = tid; i < BN * 8; i += 256) {
                int r = i >> 3, u = i & 7;
                const __half* src = ((u & 4) ? Bl : Bh) + (size_t)r * lb + (u & 3) * 8;
                cp16(db + r * 128 + ((u ^ (r & 7)) << 4), src);
            }
        }
        asm volatile("cp.async.commit_group;");
    };

    issue(0, 0); issue(1, 1); issue(2, 2);

    for (int cc = 0; cc < tot; cc++) {
        asm volatile("cp.async.wait_group 2;");
        __syncthreads();

        const int s = cc % ST;
        uint32_t aBase = s2u(sAb + s * ASTG);
        uint32_t bBase = s2u(sBb + s * BSTG);

        #pragma unroll
        for (int ks = 0; ks < 2; ks++) {
            // B frags for all n-tiles at this k16 step
            uint32_t bh[2][4], bl[2][4];
            #pragma unroll
            for (int ntp = 0; ntp < 2; ntp++) {
                int brow = wn * 32 + ntp * 16 + (lane & 7) + ((lane & 16) >> 1);
                int u = ks * 2 + ((lane & 8) >> 3);
                ldmx4(bh[ntp], bBase + brow * 128 + (((u)     ^ (brow & 7)) << 4));
                ldmx4(bl[ntp], bBase + brow * 128 + (((u + 4) ^ (brow & 7)) << 4));
            }
            #pragma unroll
            for (int mp = 0; mp < MT / 2; mp++) {
                uint32_t ah[2][4], al[2][4];
                #pragma unroll
                for (int q = 0; q < 2; q++) {
                    int arow = wm * (MT * 16) + (mp * 2 + q) * 16 + (lane & 15);
                    int u = ks * 2 + ((lane & 16) >> 4);
                    ldmx4(ah[q], aBase + arow * 128 + (((u)     ^ (arow & 7)) << 4));
                    ldmx4(al[q], aBase + arow * 128 + (((u + 4) ^ (arow & 7)) << 4));
                }
                // per-accumulator order: hh -> hl -> lh
                #pragma unroll
                for (int q = 0; q < 2; q++)
                    #pragma unroll
                    for (int nt = 0; nt < 4; nt++)
                        mma_f16(acc[mp * 2 + q][nt], ah[q],
                                bh[nt >> 1][(nt & 1) * 2], bh[nt >> 1][(nt & 1) * 2 + 1]);
                #pragma unroll
                for (int q = 0; q < 2; q++)
                    #pragma unroll
                    for (int nt = 0; nt < 4; nt++)
                        mma_f16(acc[mp * 2 + q][nt], ah[q],
                                bl[nt >> 1][(nt & 1) * 2], bl[nt >> 1][(nt & 1) * 2 + 1]);
                #pragma unroll
                for (int q = 0; q < 2; q++)
                    #pragma unroll
                    for (int nt = 0; nt < 4; nt++)
                        mma_f16(acc[mp * 2 + q][nt], al[q],
                                bh[nt >> 1][(nt & 1) * 2], bh[nt >> 1][(nt & 1) * 2 + 1]);
            }
        }
        __syncthreads();
        issue(cc + 3, s);
    }

    // epilogue
    #pragma unroll
    for (int mt = 0; mt < MT; mt++) {
        int r = row0 + wm * (MT * 16) + mt * 16 + g;
        #pragma unroll
        for (int nt = 0; nt < 4; nt++) {
            int cI = n0 + wn * 32 + nt * 8 + tig * 2;
            float v[4] = {acc[mt][nt][0], acc[mt][nt][1],
                          acc[mt][nt][2], acc[mt][nt][3]};
            size_t o0 = (size_t)r * ldc + cI;
            size_t o1 = o0 + (size_t)8 * ldc;
            if (act) {
                __half hh[4], hl[4];
                #pragma unroll
                for (int q = 0; q < 4; q++) {
                    float nn = sqrtf(v[q] * v[q] + 1e-8f);
                    float sg = 1.0f / (1.0f + expf(-nn));
                    float rr = v[q] * sg / nn;
                    hh[q] = __float2half_rn(rr);
                    hl[q] = __float2half_rn(rr - __half2float(hh[q]));
                }
                *(__half2*)(Ch + o0) = __halves2half2(hh[0], hh[1]);
                *(__half2*)(Ch + o1) = __halves2half2(hh[2], hh[3]);
                *(__half2*)(Cl + o0) = __halves2half2(hl[0], hl[1]);
                *(__half2*)(Cl + o1) = __halves2half2(hl[2], hl[3]);
            } else {
                *(float2*)(C + o0) = make_float2(v[0], v[1]);
                *(float2*)(C + o1) = make_float2(v[2], v[3]);
            }
        }
    }
}

// ---------------- fused weight prep: 12 segments, transposed, fp16 hi/lo ---
__global__ void conv_w_all(const float* __restrict__ w1, const float* __restrict__ w2,
                           const float* __restrict__ w3, const float* __restrict__ wb,
                           __half* __restrict__ t1h, __half* __restrict__ t1l,
                           __half* __restrict__ t2h, __half* __restrict__ t2l,
                           __half* __restrict__ t3h, __half* __restrict__ t3l,
                           __half* __restrict__ tbh, __half* __restrict__ tbl) {
    int idx = blockIdx.x * 256 + threadIdx.x;
    if (idx >= 774144) return;
    const int ends[12] = {131072, 163840, 172032, 434176, 499712, 516096,
                          647168, 679936, 688128, 753664, 770048, 774144};
    const int Ks[12]   = {256, 128, 64, 512, 256, 128, 512, 256, 128, 256, 128, 64};
    const int Ns[12]   = {512, 256, 128, 512, 256, 128, 256, 128, 64, 256, 128, 64};
    int sidx = 0;
    while (idx >= ends[sidx]) sidx++;
    int start = sidx ? ends[sidx - 1] : 0;
    const float* src; __half *dh, *dl; int tbase;
    if (sidx < 3)      { src = w1; dh = t1h; dl = t1l; tbase = 0; }
    else if (sidx < 6) { src = w2; dh = t2h; dl = t2l; tbase = 172032; }
    else if (sidx < 9) { src = w3; dh = t3h; dl = t3l; tbase = 516096; }
    else               { src = wb; dh = tbh; dl = tbl; tbase = 688128; }
    int segoff = start - tbase;
    int local  = idx - start;
    int K = Ks[sidx], Nout = Ns[sidx];
    int u = local / Nout, v = local - u * Nout;
    float val = src[segoff + local] * (1.0f / sqrtf((float)K));
    __half hi = __float2half_rn(val);
    size_t o = segoff + (size_t)v * K + u;
    dh[o] = hi;
    dl[o] = __float2half_rn(val - __half2float(hi));
}

// ---------------- x interleaved -> planar fp16 hi/lo ----------------
__global__ void to_planar_kernel(const float* __restrict__ x) {
    int idx = blockIdx.x * 256 + threadIdx.x;
    if (idx >= NROWS * DIN) return;
    int n = idx / DIN, j = idx - n * DIN;
    int src;
    if (j < 256) {
        src = j;
    } else if (j < 640) {
        int p = j - 256;
        src = 256 + (p & 127) * 3 + (p >> 7);
    } else {
        int p = j - 640;
        src = 640 + (p & 63) * 5 + (p >> 6);
    }
    float v = x[(size_t)n * DIN + src];
    __half hi = __float2half_rn(v);
    g_xph[idx] = hi;
    g_xpl[idx] = __float2half_rn(v - __half2float(hi));
}

// ---------------- NormActivation l>0: fp32 in -> fp16 hi/lo planes out -----
template <int L>
__global__ void normact_kernel(const float* __restrict__ H,
                               __half* __restrict__ Hh, __half* __restrict__ Hl,
                               int o, int m) {
    int idx = blockIdx.x * 256 + threadIdx.x;
    if (idx >= NROWS * m) return;
    int n = idx / m, v = idx - n * m;
    const float* p = H + (size_t)n * DH + o + v;
    float f[L];
    float s2 = 1e-8f;
    #pragma unroll
    for (int i = 0; i < L; i++) { f[i] = p[(size_t)i * m]; s2 += f[i] * f[i]; }
    float nn = sqrtf(s2);
    float sg = 1.0f / (1.0f + expf(-nn));
    float sc = sg / nn;
    #pragma unroll
    for (int i = 0; i < L; i++) {
        float r = f[i] * sc;
        __half hi = __float2half_rn(r);
        size_t off = (size_t)n * DH + o + (size_t)i * m + v;
        Hh[off] = hi;
        Hl[off] = __float2half_rn(r - __half2float(hi));
    }
}

// ---------------- BatchNorm ----------------
__global__ void bn_zero_kernel() {
    int t = threadIdx.x;
    if (t < 256) g_sum0[t] = 0.0f;
    if (t < 448) g_ssq[t]  = 0.0f;
}

__global__ void bn_reduce_kernel() {
    const int tid = threadIdx.x;
    const int r0  = blockIdx.x * 128;
    float s[4] = {0, 0, 0, 0}, q[4] = {0, 0, 0, 0};
    for (int r = 0; r < 128; r++) {
        const float* row = g_outp + (size_t)(r0 + r) * DIN;
        #pragma unroll
        for (int k = 0; k < 4; k++) {
            int j = tid + (k << 8);
            if (j < DIN) {
                float v = row[j];
                s[k] += v;
                q[k] += v * v;
            }
        }
    }
    #pragma unroll
    for (int k = 0; k < 4; k++) {
        int j = tid + (k << 8);
        if (j >= DIN) continue;
        if (j < 256) {
            atomicAdd(&g_sum0[j], s[k]);
            atomicAdd(&g_ssq[j], q[k]);
        } else if (j < 640) {
            atomicAdd(&g_ssq[256 + ((j - 256) & 127)], q[k]);
        } else {
            atomicAdd(&g_ssq[384 + ((j - 640) & 63)], q[k]);
        }
    }
}

__global__ void bn_apply_kernel(const float* __restrict__ bnw,
                                const float* __restrict__ bnb,
                                float* __restrict__ out) {
    int idx = blockIdx.x * 256 + threadIdx.x;
    if (idx >= NROWS * DIN) return;
    int n = idx / DIN, jo = idx - n * DIN;
    const float invN = 1.0f / (float)NROWS;
    float g;
    if (jo < 256) {
        float f   = g_outp[(size_t)n * DIN + jo];
        float mu  = g_sum0[jo] * invN;
        float var = g_ssq[jo] * invN - mu * mu;
        g = (f - mu) * bnw[jo] * rsqrtf(var + 1e-5f) + bnb[jo];
    } else if (jo < 640) {
        int p = jo - 256, v = p / 3, i = p - v * 3;
        float f  = g_outp[(size_t)n * DIN + 256 + (i << 7) + v];
        float n2 = g_ssq[256 + v] * (invN * (1.0f / 3.0f));
        g = f * bnw[256 + v] * rsqrtf(n2 + 1e-5f);
    } else {
        int p = jo - 640, v = p / 5, i = p - v * 5;
        float f  = g_outp[(size_t)n * DIN + 640 + (i << 6) + v];
        float n2 = g_ssq[384 + v] * (invN * (1.0f / 5.0f));
        g = f * bnw[384 + v] * rsqrtf(n2 + 1e-5f);
    }
    out[idx] = g;
}

// ---------------- launch ----------------
#define SMEM128 (3 * (128 * 128 + 128 * 128))   // 98304
#define SMEM64  (3 * (128 * 128 + 64 * 128))    // 73728

extern "C" void kernel_launch(void* const* d_in, const int* in_sizes, int n_in,
                              void* d_out, int out_size) {
    const float* x   = (const float*)d_in[0];
    const float* w1  = (const float*)d_in[1];
    const float* w2  = (const float*)d_in[2];
    const float* w3  = (const float*)d_in[3];
    const float* wb  = (const float*)d_in[4];
    const float* bnw = (const float*)d_in[5];
    const float* bnb = (const float*)d_in[6];
    float* out = (float*)d_out;

    static int inited = 0;
    static cudaStream_t s1, s2, s3;
    static cudaEvent_t e0, eb1, eb2, eb3;
    if (!inited) {
        cudaFuncSetAttribute(gemm_f16<128>, cudaFuncAttributeMaxDynamicSharedMemorySize, SMEM128);
        cudaFuncSetAttribute(gemm_f16<64>,  cudaFuncAttributeMaxDynamicSharedMemorySize, SMEM64);
        cudaStreamCreateWithFlags(&s1, cudaStreamNonBlocking);
        cudaStreamCreateWithFlags(&s2, cudaStreamNonBlocking);
        cudaStreamCreateWithFlags(&s3, cudaStreamNonBlocking);
        cudaEventCreateWithFlags(&e0,  cudaEventDisableTiming);
        cudaEventCreateWithFlags(&eb1, cudaEventDisableTiming);
        cudaEventCreateWithFlags(&eb2, cudaEventDisableTiming);
        cudaEventCreateWithFlags(&eb3, cudaEventDisableTiming);
        inited = 1;
    }

    __half *xph, *xpl, *h1h, *h1l, *h2h, *h2l;
    __half *w1h, *w1l, *w2h, *w2l, *w3h, *w3l, *wbh, *wbl;
    float *h1, *h2, *op;
    cudaGetSymbolAddress((void**)&xph, g_xph);
    cudaGetSymbolAddress((void**)&xpl, g_xpl);
    cudaGetSymbolAddress((void**)&h1,  g_h1);
    cudaGetSymbolAddress((void**)&h1h, g_h1h);
    cudaGetSymbolAddress((void**)&h1l, g_h1l);
    cudaGetSymbolAddress((void**)&h2,  g_h2);
    cudaGetSymbolAddress((void**)&h2h, g_h2h);
    cudaGetSymbolAddress((void**)&h2l, g_h2l);
    cudaGetSymbolAddress((void**)&op,  g_outp);
    cudaGetSymbolAddress((void**)&w1h, g_wt1h);
    cudaGetSymbolAddress((void**)&w1l, g_wt1l);
    cudaGetSymbolAddress((void**)&w2h, g_wt2h);
    cudaGetSymbolAddress((void**)&w2l, g_wt2l);
    cudaGetSymbolAddress((void**)&w3h, g_wt3h);
    cudaGetSymbolAddress((void**)&w3l, g_wt3l);
    cudaGetSymbolAddress((void**)&wbh, g_wtbh);
    cudaGetSymbolAddress((void**)&wbl, g_wtbl);

    auto gemm = [&](cudaStream_t st,
                    const __half* Ah, const __half* Al, int lda, size_t sAz,
                    const __half* Bh, const __half* Bl,
                    float* Cf, __half* Chp, __half* Clp, int ldc, size_t sCz,
                    int K, int Nout, int nz, int act) {
        if (Nout >= 128) {
            dim3 grid(Nout / 128, NROWS / 128, nz);
            gemm_f16<128><<<grid, 256, SMEM128, st>>>(
                Ah, Al, lda, sAz, Bh, Bl, K, K / 32,
                Ah, Al, lda, sAz, Bh, Bl, K, 0,
                Cf, Chp, Clp, ldc, sCz, act);
        } else {
            dim3 grid(Nout / 64, NROWS / 128, nz);
            gemm_f16<64><<<grid, 256, SMEM64, st>>>(
                Ah, Al, lda, sAz, Bh, Bl, K, K / 32,
                Ah, Al, lda, sAz, Bh, Bl, K, 0,
                Cf, Chp, Clp, ldc, sCz, act);
        }
    };
    auto gemm2 = [&](cudaStream_t st,
                     const __half* A1hp, const __half* A1lp, int lda1, size_t sAz1,
                     const __half* B1hp, const __half* B1lp, int K1,
                     const __half* A2hp, const __half* A2lp, int lda2, size_t sAz2,
                     const __half* B2hp, const __half* B2lp, int K2,
                     float* Cf, int ldc, size_t sCz, int Nout, int nz) {
        if (Nout >= 128) {
            dim3 grid(Nout / 128, NROWS / 128, nz);
            gemm_f16<128><<<grid, 256, SMEM128, st>>>(
                A1hp, A1lp, lda1, sAz1, B1hp, B1lp, K1, K1 / 32,
                A2hp, A2lp, lda2, sAz2, B2hp, B2lp, K2, K2 / 32,
                Cf, (__half*)Cf, (__half*)Cf, ldc, sCz, 0);
        } else {
            dim3 grid(Nout / 64, NROWS / 128, nz);
            gemm_f16<64><<<grid, 256, SMEM64, st>>>(
                A1hp, A1lp, lda1, sAz1, B1hp, B1lp, K1, K1 / 32,
                A2hp, A2lp, lda2, sAz2, B2hp, B2lp, K2, K2 / 32,
                Cf, (__half*)Cf, (__half*)Cf, ldc, sCz, 0);
        }
    };

    // ---- prologue on the capture stream ----
    conv_w_all<<<3024, 256>>>(w1, w2, w3, wb, w1h, w1l, w2h, w2l, w3h, w3l, wbh, wbl);
    to_planar_kernel<<<(NROWS * DIN) / 256, 256>>>(x);
    bn_zero_kernel<<<1, 512>>>();
    cudaEventRecord(e0, 0);

    cudaStreamWaitEvent(s1, e0, 0);
    cudaStreamWaitEvent(s2, e0, 0);
    cudaStreamWaitEvent(s3, e0, 0);

    // l0 chain (s1): scalar normact fused into epilogues (writes half planes)
    gemm(s1, xph, xpl, DIN, 0, w1h, w1l, 0, h1h, h1l, DH, 0, 256, 512, 1, 1);
    gemm(s1, h1h, h1l, DH, 0, w2h, w2l, 0, h2h, h2l, DH, 0, 512, 512, 1, 1);
    gemm2(s1, h2h, h2l, DH, 0, w3h, w3l, 512,
          xph, xpl, DIN, 0, wbh, wbl, 256, op, DIN, 0, 256, 1);
    cudaEventRecord(eb1, s1);

    // l1 chain (s2)
    gemm(s2, xph + 256, xpl + 256, DIN, 128, w1h + 131072, w1l + 131072,
         h1 + 512, 0, 0, DH, 256, 128, 256, 3, 0);
    normact_kernel<3><<<(NROWS * 256) / 256, 256, 0, s2>>>(h1, h1h, h1l, 512, 256);
    gemm(s2, h1h + 512, h1l + 512, DH, 256, w2h + 262144, w2l + 262144,
         h2 + 512, 0, 0, DH, 256, 256, 256, 3, 0);
    normact_kernel<3><<<(NROWS * 256) / 256, 256, 0, s2>>>(h2, h2h, h2l, 512, 256);
    gemm2(s2, h2h + 512, h2l + 512, DH, 256, w3h + 131072, w3l + 131072, 256,
          xph + 256, xpl + 256, DIN, 128, wbh + 65536, wbl + 65536, 128,
          op + 256, DIN, 128, 128, 3);
    cudaEventRecord(eb2, s2);

    // l2 chain (s3)
    gemm(s3, xph + 640, xpl + 640, DIN, 64, w1h + 163840, w1l + 163840,
         h1 + 1280, 0, 0, DH, 128, 64, 128, 5, 0);
    normact_kernel<5><<<(NROWS * 128) / 256, 256, 0, s3>>>(h1, h1h, h1l, 1280, 128);
    gemm(s3, h1h + 1280, h1l + 1280, DH, 128, w2h + 327680, w2l + 327680,
         h2 + 1280, 0, 0, DH, 128, 128, 128, 5, 0);
    normact_kernel<5><<<(NROWS * 128) / 256, 256, 0, s3>>>(h2, h2h, h2l, 1280, 128);
    gemm2(s3, h2h + 1280, h2l + 1280, DH, 128, w3h + 163840, w3l + 163840, 128,
          xph + 640, xpl + 640, DIN, 64, wbh + 81920, wbl + 81920, 64,
          op + 640, DIN, 64, 64, 5);
    cudaEventRecord(eb3, s3);

    // ---- join, then batch norm ----
    cudaStreamWaitEvent(0, eb1, 0);
    cudaStreamWaitEvent(0, eb2, 0);
    cudaStreamWaitEvent(0, eb3, 0);
    bn_reduce_kernel<<<256, 256>>>();
    bn_apply_kernel<<<(NROWS * DIN) / 256, 256>>>(bnw, bnb, out);
}